// round 6
// baseline (speedup 1.0000x reference)
#include <cuda_runtime.h>
#include <math.h>
#include <stdint.h>

// Problem constants
#define BATCH   8
#define NPTS    16384
#define NPOINT  1024
#define NSAMP   32
#define RTOT    (BATCH*NPOINT*NSAMP)   /* 262144 rows */

// ---------------- scratch (device globals; no allocations allowed) ----------
__device__ float g_x0[(size_t)RTOT*9];        // grouped+concat input  (9.4MB)
__device__ float g_y0[(size_t)64*RTOT];       // layer0 raw out [64][R] (67MB)
__device__ float g_y1[(size_t)64*RTOT];       // layer1 raw out (67MB)
__device__ float g_y2[(size_t)128*RTOT];      // layer2 raw out (134MB)
__device__ float g_part[(size_t)1024*128*2];  // per-block BN partial sums
__device__ float g_A0[64], g_C0[64];
__device__ float g_A1[64], g_C1[64];
__device__ float g_A2[128], g_C2[128];

// ---------------- FPS: one block per batch ----------------------------------
// Emits centroid coords (the farthest index BEFORE each update, start = 0).
// All distance arithmetic via *_rn intrinsics to forbid FMA contraction so we
// bit-match XLA's (sub, mul, reduce-add) lowering; argmax tie-break = lowest idx.
__global__ __launch_bounds__(1024,1) void fps_kernel(const float* __restrict__ xyz,
                                                     float* __restrict__ dout)
{
    extern __shared__ float sm[];
    float* sx = sm; float* sy = sm + NPTS; float* sz = sm + 2*NPTS;
    __shared__ float redV[32]; __shared__ int redI[32];
    __shared__ float bcx, bcy, bcz;

    int b = blockIdx.x, t = threadIdx.x;
    const float* X = xyz + (size_t)b*NPTS*3;
    for (int i = t; i < NPTS; i += 1024) {
        sx[i] = X[3*i]; sy[i] = X[3*i+1]; sz[i] = X[3*i+2];
    }
    float dist[16];
#pragma unroll
    for (int k = 0; k < 16; k++) dist[k] = 1e10f;
    __syncthreads();
    if (t == 0) { bcx = sx[0]; bcy = sy[0]; bcz = sz[0]; }
    __syncthreads();

    int lane = t & 31, w = t >> 5;
    float* co = dout + (size_t)b*NPOINT*3;

    for (int it = 0; it < NPOINT; it++) {
        float cx = bcx, cy = bcy, cz = bcz;
        if (t == 0) { co[3*it] = cx; co[3*it+1] = cy; co[3*it+2] = cz; }

        float best = -1.0f; int bi = 0;
#pragma unroll
        for (int k = 0; k < 16; k++) {
            int p = t + (k << 10);
            float dx = __fsub_rn(sx[p], cx);
            float dy = __fsub_rn(sy[p], cy);
            float dz = __fsub_rn(sz[p], cz);
            float d  = __fadd_rn(__fadd_rn(__fmul_rn(dx,dx), __fmul_rn(dy,dy)),
                                 __fmul_rn(dz,dz));
            float nd = fminf(dist[k], d);
            dist[k] = nd;
            if (nd > best) { best = nd; bi = p; }   // strict >: keeps lowest p
        }
#pragma unroll
        for (int o = 16; o > 0; o >>= 1) {
            float ov = __shfl_down_sync(0xffffffffu, best, o);
            int   oi = __shfl_down_sync(0xffffffffu, bi, o);
            if (ov > best || (ov == best && oi < bi)) { best = ov; bi = oi; }
        }
        if (lane == 0) { redV[w] = best; redI[w] = bi; }
        __syncthreads();
        if (w == 0) {
            float v = redV[lane]; int i2 = redI[lane];
#pragma unroll
            for (int o = 16; o > 0; o >>= 1) {
                float ov = __shfl_down_sync(0xffffffffu, v,  o);
                int   oi = __shfl_down_sync(0xffffffffu, i2, o);
                if (ov > v || (ov == v && oi < i2)) { v = ov; i2 = oi; }
            }
            if (lane == 0) { bcx = sx[i2]; bcy = sy[i2]; bcz = sz[i2]; }
        }
        __syncthreads();
    }
}

// ---------------- Ball query + gather + concat: one warp per centroid -------
__global__ __launch_bounds__(256) void bq_kernel(const float* __restrict__ xyz,
                                                 const float* __restrict__ pts,
                                                 const float* __restrict__ cent,
                                                 float* __restrict__ x0)
{
    __shared__ int sbuf[8][NSAMP];
    int w = threadIdx.x >> 5, lane = threadIdx.x & 31;
    int wg = blockIdx.x * 8 + w;          // 0..8191 = b*1024 + p
    int b  = wg >> 10;
    const float* X = xyz + (size_t)b*NPTS*3;

    float cx = cent[3*wg], cy = cent[3*wg+1], cz = cent[3*wg+2];
    const float R2 = (float)(0.2*0.2);    // == jnp's f32(0.04), NOT 0.2f*0.2f
    float sc = __fadd_rn(__fadd_rn(__fmul_rn(cx,cx), __fmul_rn(cy,cy)),
                         __fmul_rn(cz,cz));
    sbuf[w][lane] = 0;
    __syncwarp();

    int count = 0;
    for (int base = 0; base < NPTS; base += 32) {
        int p = base + lane;
        float x = X[3*p], y = X[3*p+1], z = X[3*p+2];
        float dot = __fadd_rn(__fadd_rn(__fmul_rn(cx,x), __fmul_rn(cy,y)),
                              __fmul_rn(cz,z));
        float sx2 = __fadd_rn(__fadd_rn(__fmul_rn(x,x), __fmul_rn(y,y)),
                              __fmul_rn(z,z));
        float d2  = __fadd_rn(__fsub_rn(sc, __fmul_rn(2.0f, dot)), sx2);
        bool in = d2 < R2;
        unsigned m = __ballot_sync(0xffffffffu, in);
        if (in) {
            int pos = count + __popc(m & ((1u << lane) - 1u));
            if (pos < NSAMP) sbuf[w][pos] = p;
        }
        count += __popc(m);
        if (count >= NSAMP) break;        // warp-uniform
    }
    __syncwarp();

    int idx = sbuf[w][lane];              // padded slots hold 0 (== torch semantics)
    const float* PT = pts + (size_t)b*NPTS*6;
    float* o = x0 + ((size_t)wg*NSAMP + lane)*9;
    o[0] = __fsub_rn(X[3*idx],   cx);
    o[1] = __fsub_rn(X[3*idx+1], cy);
    o[2] = __fsub_rn(X[3*idx+2], cz);
#pragma unroll
    for (int k = 0; k < 6; k++) o[3+k] = PT[6*idx+k];
}

// ---------------- Layer 0: 9 -> 64, row-major in, channel-major out ---------
__global__ __launch_bounds__(256) void conv0_kernel(const float* __restrict__ x0,
                                                    const float* __restrict__ W,
                                                    const float* __restrict__ B,
                                                    float* __restrict__ y,
                                                    float* __restrict__ part)
{
    __shared__ float xs[256*9];
    __shared__ float sr1[4][64], sr2[4][64];
    int t = threadIdx.x; size_t r0 = (size_t)blockIdx.x * 256;
    for (int i = t; i < 256*9; i += 256) xs[i] = x0[r0*9 + i];

    int ch = t & 63, rg = t >> 6;
    float wv[9];
#pragma unroll
    for (int k = 0; k < 9; k++) wv[k] = W[ch*9 + k];
    float bias = B[ch];
    __syncthreads();

    float s1 = 0.f, s2 = 0.f;
    float* yo = y + (size_t)ch*RTOT + r0 + rg*64;
    const float* xr = xs + rg*64*9;
    for (int i = 0; i < 64; i++) {
        float acc = bias;
#pragma unroll
        for (int k = 0; k < 9; k++) acc = fmaf(wv[k], xr[i*9 + k], acc);
        yo[i] = acc; s1 += acc; s2 = fmaf(acc, acc, s2);
    }
    sr1[rg][ch] = s1; sr2[rg][ch] = s2;
    __syncthreads();
    if (rg == 0) {
        float a  = sr1[0][ch] + sr1[1][ch] + sr1[2][ch] + sr1[3][ch];
        float c2 = sr2[0][ch] + sr2[1][ch] + sr2[2][ch] + sr2[3][ch];
        part[((size_t)blockIdx.x*64 + ch)*2]     = a;
        part[((size_t)blockIdx.x*64 + ch)*2 + 1] = c2;
    }
}

// ---------------- BN stat finalize (deterministic, double accumulation) -----
__global__ __launch_bounds__(256) void stats_kernel(const float* __restrict__ part,
                                                    int nblk, int cout,
                                                    const float* __restrict__ g,
                                                    const float* __restrict__ be,
                                                    float* __restrict__ A,
                                                    float* __restrict__ C)
{
    __shared__ double r1[256], r2[256];
    int ch = blockIdx.x, t = threadIdx.x;
    double s1 = 0.0, s2 = 0.0;
    for (int i = t; i < nblk; i += 256) {
        const float* p = part + ((size_t)i*cout + ch)*2;
        s1 += (double)p[0]; s2 += (double)p[1];
    }
    r1[t] = s1; r2[t] = s2; __syncthreads();
    for (int o = 128; o > 0; o >>= 1) {
        if (t < o) { r1[t] += r1[t+o]; r2[t] += r2[t+o]; }
        __syncthreads();
    }
    if (t == 0) {
        double n = (double)RTOT;
        double mean = r1[0] / n;
        double var  = r2[0] / n - mean*mean;
        float rstd = (float)(1.0 / sqrt(var + 1e-5));
        float a = g[ch] * rstd;
        float c = be[ch] - (float)mean * a;
        A[ch] = a; C[ch] = c;
    }
}

// ---------------- Mid conv: 64 -> COUT, prev-layer BN+ReLU fused on load ----
template<int COUT>
__global__ __launch_bounds__(COUT*4, 1)
void conv_mid_kernel(const float* __restrict__ in,  // raw prev layer [64][R]
                     const float* __restrict__ A, const float* __restrict__ C,
                     const float* __restrict__ W, const float* __restrict__ B,
                     float* __restrict__ out,       // raw this layer [COUT][R]
                     float* __restrict__ part)
{
    extern __shared__ float sm[];
    float* ins = sm;                 // [64][256]
    float* ws  = sm + 64*256;        // [COUT][65] padded
    float* sr1 = ws + COUT*65;       // [COUT][16]
    float* sr2 = sr1 + COUT*16;
    const int NT = COUT*4;
    int t = threadIdx.x; size_t r0 = (size_t)blockIdx.x * 256;

    for (int i = t; i < COUT*64; i += NT) { int o = i >> 6, c = i & 63; ws[o*65 + c] = W[i]; }
    for (int i = t; i < 64*256; i += NT) {
        int c = i >> 8, col = i & 255;
        float v = fmaf(in[(size_t)c*RTOT + r0 + col], A[c], C[c]);  // BN prev
        ins[i] = fmaxf(v, 0.f);                                     // ReLU prev
    }
    __syncthreads();

    int colg = t & 15, chg = t >> 4;       // 4 out-ch x 16 cols per thread
    float acc[4][16];
#pragma unroll
    for (int cc = 0; cc < 4; cc++) {
        float bz = B[chg*4 + cc];
#pragma unroll
        for (int j = 0; j < 16; j++) acc[cc][j] = bz;
    }
    for (int c = 0; c < 64; c++) {
        float xv[16];
#pragma unroll
        for (int j = 0; j < 16; j++) xv[j] = ins[c*256 + colg + 16*j];
#pragma unroll
        for (int cc = 0; cc < 4; cc++) {
            float wv = ws[(chg*4 + cc)*65 + c];
#pragma unroll
            for (int j = 0; j < 16; j++) acc[cc][j] = fmaf(wv, xv[j], acc[cc][j]);
        }
    }
#pragma unroll
    for (int cc = 0; cc < 4; cc++) {
        int ch = chg*4 + cc;
        float s1 = 0.f, s2 = 0.f;
        float* o = out + (size_t)ch*RTOT + r0 + colg;
#pragma unroll
        for (int j = 0; j < 16; j++) {
            float v = acc[cc][j]; o[16*j] = v; s1 += v; s2 = fmaf(v, v, s2);
        }
        sr1[ch*16 + colg] = s1; sr2[ch*16 + colg] = s2;
    }
    __syncthreads();
    for (int ch = t; ch < COUT; ch += NT) {
        float a = 0.f, b2 = 0.f;
#pragma unroll
        for (int k = 0; k < 16; k++) { a += sr1[ch*16 + k]; b2 += sr2[ch*16 + k]; }
        part[((size_t)blockIdx.x*COUT + ch)*2]     = a;
        part[((size_t)blockIdx.x*COUT + ch)*2 + 1] = b2;
    }
}

// ---------------- Final: BN2 + ReLU + max over S -> new_points --------------
__global__ __launch_bounds__(128) void maxpool_kernel(const float* __restrict__ y2,
                                                      const float* __restrict__ A,
                                                      const float* __restrict__ C,
                                                      float* __restrict__ dout)
{
    int grp = blockIdx.x, ch = threadIdx.x;
    const float4* p = reinterpret_cast<const float4*>(
        y2 + (size_t)ch*RTOT + (size_t)grp*NSAMP);
    float a = A[ch], c = C[ch], m = 0.f;   // ReLU -> max of nonneg, 0-init OK
#pragma unroll
    for (int i = 0; i < 8; i++) {
        float4 v = p[i];
        m = fmaxf(m, fmaxf(fmaxf(fmaf(v.x,a,c), fmaf(v.y,a,c)),
                           fmaxf(fmaf(v.z,a,c), fmaf(v.w,a,c))));
    }
    dout[(size_t)BATCH*NPOINT*3 + (size_t)grp*128 + ch] = m;
}

// ---------------- launch ----------------------------------------------------
extern "C" void kernel_launch(void* const* d_in, const int* in_sizes, int n_in,
                              void* d_out, int out_size)
{
    (void)in_sizes; (void)n_in; (void)out_size;
    const float* xyz = (const float*)d_in[0];
    const float* pts = (const float*)d_in[1];
    const float* w0  = (const float*)d_in[2];  const float* b0  = (const float*)d_in[3];
    const float* g0  = (const float*)d_in[4];  const float* be0 = (const float*)d_in[5];
    const float* w1  = (const float*)d_in[6];  const float* b1  = (const float*)d_in[7];
    const float* g1  = (const float*)d_in[8];  const float* be1 = (const float*)d_in[9];
    const float* w2  = (const float*)d_in[10]; const float* b2  = (const float*)d_in[11];
    const float* g2  = (const float*)d_in[12]; const float* be2 = (const float*)d_in[13];
    float* out = (float*)d_out;

    float *x0, *y0, *y1, *y2, *part, *A0, *C0, *A1, *C1, *A2, *C2;
    cudaGetSymbolAddress((void**)&x0,  g_x0);
    cudaGetSymbolAddress((void**)&y0,  g_y0);
    cudaGetSymbolAddress((void**)&y1,  g_y1);
    cudaGetSymbolAddress((void**)&y2,  g_y2);
    cudaGetSymbolAddress((void**)&part,g_part);
    cudaGetSymbolAddress((void**)&A0,  g_A0);  cudaGetSymbolAddress((void**)&C0, g_C0);
    cudaGetSymbolAddress((void**)&A1,  g_A1);  cudaGetSymbolAddress((void**)&C1, g_C1);
    cudaGetSymbolAddress((void**)&A2,  g_A2);  cudaGetSymbolAddress((void**)&C2, g_C2);

    const int FPS_SMEM = 3*NPTS*4;                               // 196608
    const int C1_SMEM  = (64*256 + 64*65  + 64*16*2)  * 4;       // 90368
    const int C2_SMEM  = (64*256 + 128*65 + 128*16*2) * 4;       // 115200
    cudaFuncSetAttribute(fps_kernel,           cudaFuncAttributeMaxDynamicSharedMemorySize, FPS_SMEM);
    cudaFuncSetAttribute(conv_mid_kernel<64>,  cudaFuncAttributeMaxDynamicSharedMemorySize, C1_SMEM);
    cudaFuncSetAttribute(conv_mid_kernel<128>, cudaFuncAttributeMaxDynamicSharedMemorySize, C2_SMEM);

    fps_kernel<<<BATCH, 1024, FPS_SMEM>>>(xyz, out);
    bq_kernel<<<BATCH*NPOINT/8, 256>>>(xyz, pts, out, x0);
    conv0_kernel<<<RTOT/256, 256>>>(x0, w0, b0, y0, part);
    stats_kernel<<<64, 256>>>(part, RTOT/256, 64, g0, be0, A0, C0);
    conv_mid_kernel<64><<<RTOT/256, 256, C1_SMEM>>>(y0, A0, C0, w1, b1, y1, part);
    stats_kernel<<<64, 256>>>(part, RTOT/256, 64, g1, be1, A1, C1);
    conv_mid_kernel<128><<<RTOT/256, 512, C2_SMEM>>>(y1, A1, C1, w2, b2, y2, part);
    stats_kernel<<<128, 256>>>(part, RTOT/256, 128, g2, be2, A2, C2);
    maxpool_kernel<<<BATCH*NPOINT, 128>>>(y2, A2, C2, out);
}

// round 8
// speedup vs baseline: 1.0877x; 1.0877x over previous
#include <cuda_runtime.h>
#include <math.h>
#include <stdint.h>

// Problem constants
#define BATCH   8
#define NPTS    16384
#define NPOINT  1024
#define NSAMP   32
#define RTOT    (BATCH*NPOINT*NSAMP)   /* 262144 rows */
#define FPB     8                      /* FPS CTAs per batch (cluster size) */
#define PPC     (NPTS/FPB)             /* 2048 points per CTA */

// ---------------- scratch (device globals; no allocations allowed) ----------
__device__ float g_x0[(size_t)RTOT*9];        // grouped+concat input  (9.4MB)
__device__ float g_y0[(size_t)64*RTOT];       // layer0 raw out [64][R] (67MB)
__device__ float g_y1[(size_t)64*RTOT];       // layer1 raw out (67MB)
__device__ float g_gmax[(size_t)BATCH*NPOINT*128]; // per-group raw max (4MB)
__device__ float g_part[(size_t)1024*128*2];  // per-block BN partial sums
__device__ float g_A0[64], g_C0[64];
__device__ float g_A1[64], g_C1[64];
__device__ float g_A2[128], g_C2[128];

__device__ __forceinline__ uint32_t s2u(const void* p) {
    return (uint32_t)__cvta_generic_to_shared(p);
}

// ---------------- FPS: 8-CTA cluster per batch -------------------------------
// Points register-resident (2/thread). Per iter: local argmax reduce, leader
// broadcasts candidate record to all cluster CTAs via st.shared::cluster,
// one cluster barrier (double-buffered slots), all threads scan 8 records in
// rank order. Arithmetic sequence identical to the passing single-CTA version
// (bit-exact vs XLA); tie-break = lowest global index at every level.
__global__ __launch_bounds__(1024,1) __cluster_dims__(FPB,1,1)
void fps_cluster_kernel(const float* __restrict__ xyz, float* __restrict__ dout)
{
    __shared__ float sxl[PPC], syl[PPC], szl[PPC];
    __shared__ float redV[32]; __shared__ int redI[32];
    __shared__ __align__(16) float cand[2][FPB][8]; // [parity][rank][{v,x,y,z,idx}]

    int t = threadIdx.x;
    unsigned rank; asm("mov.u32 %0, %%cluster_ctarank;" : "=r"(rank));
    int b = blockIdx.x / FPB;
    const float* X = xyz + (size_t)b*NPTS*3;
    int base = (int)rank * PPC;

    int p0 = base + t, p1 = p0 + 1024;
    float x0v = X[3*p0], y0v = X[3*p0+1], z0v = X[3*p0+2];
    float x1v = X[3*p1], y1v = X[3*p1+1], z1v = X[3*p1+2];
    sxl[t]       = x0v; syl[t]       = y0v; szl[t]       = z0v;
    sxl[t+1024]  = x1v; syl[t+1024]  = y1v; szl[t+1024]  = z1v;
    float d0 = 1e10f, d1 = 1e10f;
    float cx = X[0], cy = X[1], cz = X[2];   // deterministic start at index 0

    uint32_t sb = s2u(&cand[0][rank][0]);    // local addr of my slot, parity 0
    int lane = t & 31, w = t >> 5;
    float* co = dout + (size_t)b*NPOINT*3;

    __syncthreads();
    asm volatile("barrier.cluster.arrive.aligned;" ::: "memory");
    asm volatile("barrier.cluster.wait.aligned;"   ::: "memory");

    for (int it = 0; it < NPOINT; it++) {
        if (rank == 0 && t == 0) { co[3*it] = cx; co[3*it+1] = cy; co[3*it+2] = cz; }

        // exact XLA lowering: sub, mul, add-add (no FMA contraction)
        float dx = __fsub_rn(x0v, cx), dy = __fsub_rn(y0v, cy), dz = __fsub_rn(z0v, cz);
        float d  = __fadd_rn(__fadd_rn(__fmul_rn(dx,dx), __fmul_rn(dy,dy)), __fmul_rn(dz,dz));
        d0 = fminf(d0, d);
        dx = __fsub_rn(x1v, cx); dy = __fsub_rn(y1v, cy); dz = __fsub_rn(z1v, cz);
        d  = __fadd_rn(__fadd_rn(__fmul_rn(dx,dx), __fmul_rn(dy,dy)), __fmul_rn(dz,dz));
        d1 = fminf(d1, d);

        float best = d0; int bi = p0;
        if (d1 > best) { best = d1; bi = p1; }   // strict >: lowest idx on ties

#pragma unroll
        for (int o = 16; o > 0; o >>= 1) {
            float ov = __shfl_down_sync(0xffffffffu, best, o);
            int   oi = __shfl_down_sync(0xffffffffu, bi, o);
            if (ov > best || (ov == best && oi < bi)) { best = ov; bi = oi; }
        }
        if (lane == 0) { redV[w] = best; redI[w] = bi; }
        __syncthreads();

        int par = it & 1;
        if (w == 0) {
            float v = redV[lane]; int i2 = redI[lane];
#pragma unroll
            for (int o = 16; o > 0; o >>= 1) {
                float ov = __shfl_down_sync(0xffffffffu, v,  o);
                int   oi = __shfl_down_sync(0xffffffffu, i2, o);
                if (ov > v || (ov == v && oi < i2)) { v = ov; i2 = oi; }
            }
            if (lane == 0) {
                int loc = i2 - base;
                float lx = sxl[loc], ly = syl[loc], lz = szl[loc];
                uint32_t src = sb + (uint32_t)par * (FPB*8*4);
#pragma unroll
                for (int r = 0; r < FPB; r++) {
                    uint32_t ra;
                    asm volatile("mapa.shared::cluster.u32 %0, %1, %2;"
                                 : "=r"(ra) : "r"(src), "r"(r));
                    asm volatile("st.shared::cluster.b32 [%0],    %1;" :: "r"(ra), "f"(v)  : "memory");
                    asm volatile("st.shared::cluster.b32 [%0+4],  %1;" :: "r"(ra), "f"(lx) : "memory");
                    asm volatile("st.shared::cluster.b32 [%0+8],  %1;" :: "r"(ra), "f"(ly) : "memory");
                    asm volatile("st.shared::cluster.b32 [%0+12], %1;" :: "r"(ra), "f"(lz) : "memory");
                    asm volatile("st.shared::cluster.b32 [%0+16], %1;" :: "r"(ra), "r"(i2) : "memory");
                }
            }
        }
        // release-arrive orders the DSMEM stores; acquire-wait makes them visible
        asm volatile("barrier.cluster.arrive.aligned;" ::: "memory");
        asm volatile("barrier.cluster.wait.aligned;"   ::: "memory");

        // all threads scan 8 records in rank order (broadcast LDS)
        float bv = cand[par][0][0];
        int bidx = __float_as_int(cand[par][0][4]);
        int br = 0;
#pragma unroll
        for (int r = 1; r < FPB; r++) {
            float vr = cand[par][r][0];
            int   ir = __float_as_int(cand[par][r][4]);
            if (vr > bv || (vr == bv && ir < bidx)) { bv = vr; bidx = ir; br = r; }
        }
        cx = cand[par][br][1]; cy = cand[par][br][2]; cz = cand[par][br][3];
    }
}

// ---------------- Ball query + gather + concat: one warp per centroid -------
__global__ __launch_bounds__(256) void bq_kernel(const float* __restrict__ xyz,
                                                 const float* __restrict__ pts,
                                                 const float* __restrict__ cent,
                                                 float* __restrict__ x0)
{
    __shared__ int sbuf[8][NSAMP];
    int w = threadIdx.x >> 5, lane = threadIdx.x & 31;
    int wg = blockIdx.x * 8 + w;
    int b  = wg >> 10;
    const float* X = xyz + (size_t)b*NPTS*3;

    float cx = cent[3*wg], cy = cent[3*wg+1], cz = cent[3*wg+2];
    const float R2 = (float)(0.2*0.2);    // f32(0.04), NOT 0.2f*0.2f
    float sc = __fadd_rn(__fadd_rn(__fmul_rn(cx,cx), __fmul_rn(cy,cy)),
                         __fmul_rn(cz,cz));
    sbuf[w][lane] = 0;
    __syncwarp();

    int count = 0;
    for (int base = 0; base < NPTS; base += 32) {
        int p = base + lane;
        float x = X[3*p], y = X[3*p+1], z = X[3*p+2];
        float dot = __fadd_rn(__fadd_rn(__fmul_rn(cx,x), __fmul_rn(cy,y)),
                              __fmul_rn(cz,z));
        float sx2 = __fadd_rn(__fadd_rn(__fmul_rn(x,x), __fmul_rn(y,y)),
                              __fmul_rn(z,z));
        float d2  = __fadd_rn(__fsub_rn(sc, __fmul_rn(2.0f, dot)), sx2);
        bool in = d2 < R2;
        unsigned m = __ballot_sync(0xffffffffu, in);
        if (in) {
            int pos = count + __popc(m & ((1u << lane) - 1u));
            if (pos < NSAMP) sbuf[w][pos] = p;
        }
        count += __popc(m);
        if (count >= NSAMP) break;        // warp-uniform
    }
    __syncwarp();

    int idx = sbuf[w][lane];
    const float* PT = pts + (size_t)b*NPTS*6;
    float* o = x0 + ((size_t)wg*NSAMP + lane)*9;
    o[0] = __fsub_rn(X[3*idx],   cx);
    o[1] = __fsub_rn(X[3*idx+1], cy);
    o[2] = __fsub_rn(X[3*idx+2], cz);
#pragma unroll
    for (int k = 0; k < 6; k++) o[3+k] = PT[6*idx+k];
}

// ---------------- Layer 0: 9 -> 64, row-major in, channel-major out ---------
__global__ __launch_bounds__(256) void conv0_kernel(const float* __restrict__ x0,
                                                    const float* __restrict__ W,
                                                    const float* __restrict__ B,
                                                    float* __restrict__ y,
                                                    float* __restrict__ part)
{
    __shared__ float xs[256*9];
    __shared__ float sr1[4][64], sr2[4][64];
    int t = threadIdx.x; size_t r0 = (size_t)blockIdx.x * 256;
    for (int i = t; i < 256*9; i += 256) xs[i] = x0[r0*9 + i];

    int ch = t & 63, rg = t >> 6;
    float wv[9];
#pragma unroll
    for (int k = 0; k < 9; k++) wv[k] = W[ch*9 + k];
    float bias = B[ch];
    __syncthreads();

    float s1 = 0.f, s2 = 0.f;
    float* yo = y + (size_t)ch*RTOT + r0 + rg*64;
    const float* xr = xs + rg*64*9;
    for (int i = 0; i < 64; i++) {
        float acc = bias;
#pragma unroll
        for (int k = 0; k < 9; k++) acc = fmaf(wv[k], xr[i*9 + k], acc);
        yo[i] = acc; s1 += acc; s2 = fmaf(acc, acc, s2);
    }
    sr1[rg][ch] = s1; sr2[rg][ch] = s2;
    __syncthreads();
    if (rg == 0) {
        float a  = sr1[0][ch] + sr1[1][ch] + sr1[2][ch] + sr1[3][ch];
        float c2 = sr2[0][ch] + sr2[1][ch] + sr2[2][ch] + sr2[3][ch];
        part[((size_t)blockIdx.x*64 + ch)*2]     = a;
        part[((size_t)blockIdx.x*64 + ch)*2 + 1] = c2;
    }
}

// ---------------- BN stat finalize (deterministic, double accumulation) -----
__global__ __launch_bounds__(256) void stats_kernel(const float* __restrict__ part,
                                                    int nblk, int cout,
                                                    const float* __restrict__ g,
                                                    const float* __restrict__ be,
                                                    float* __restrict__ A,
                                                    float* __restrict__ C)
{
    __shared__ double r1[256], r2[256];
    int ch = blockIdx.x, t = threadIdx.x;
    double s1 = 0.0, s2 = 0.0;
    for (int i = t; i < nblk; i += 256) {
        const float* p = part + ((size_t)i*cout + ch)*2;
        s1 += (double)p[0]; s2 += (double)p[1];
    }
    r1[t] = s1; r2[t] = s2; __syncthreads();
    for (int o = 128; o > 0; o >>= 1) {
        if (t < o) { r1[t] += r1[t+o]; r2[t] += r2[t+o]; }
        __syncthreads();
    }
    if (t == 0) {
        double n = (double)RTOT;
        double mean = r1[0] / n;
        double var  = r2[0] / n - mean*mean;
        float rstd = (float)(1.0 / sqrt(var + 1e-5));
        float a = g[ch] * rstd;
        float c = be[ch] - (float)mean * a;
        A[ch] = a; C[ch] = c;
    }
}

// ---------------- Mid conv: 64 -> 64, prev-layer BN+ReLU fused on load ------
template<int COUT>
__global__ __launch_bounds__(COUT*4, 1)
void conv_mid_kernel(const float* __restrict__ in,
                     const float* __restrict__ A, const float* __restrict__ C,
                     const float* __restrict__ W, const float* __restrict__ B,
                     float* __restrict__ out,
                     float* __restrict__ part)
{
    extern __shared__ float sm[];
    float* ins = sm;                 // [64][256]
    float* ws  = sm + 64*256;        // [COUT][65] padded
    float* sr1 = ws + COUT*65;       // [COUT][16]
    float* sr2 = sr1 + COUT*16;
    const int NT = COUT*4;
    int t = threadIdx.x; size_t r0 = (size_t)blockIdx.x * 256;

    for (int i = t; i < COUT*64; i += NT) { int o = i >> 6, c = i & 63; ws[o*65 + c] = W[i]; }
    for (int i = t; i < 64*256; i += NT) {
        int c = i >> 8, col = i & 255;
        float v = fmaf(in[(size_t)c*RTOT + r0 + col], A[c], C[c]);
        ins[i] = fmaxf(v, 0.f);
    }
    __syncthreads();

    int colg = t & 15, chg = t >> 4;
    float acc[4][16];
#pragma unroll
    for (int cc = 0; cc < 4; cc++) {
        float bz = B[chg*4 + cc];
#pragma unroll
        for (int j = 0; j < 16; j++) acc[cc][j] = bz;
    }
    for (int c = 0; c < 64; c++) {
        float xv[16];
#pragma unroll
        for (int j = 0; j < 16; j++) xv[j] = ins[c*256 + colg + 16*j];
#pragma unroll
        for (int cc = 0; cc < 4; cc++) {
            float wv = ws[(chg*4 + cc)*65 + c];
#pragma unroll
            for (int j = 0; j < 16; j++) acc[cc][j] = fmaf(wv, xv[j], acc[cc][j]);
        }
    }
#pragma unroll
    for (int cc = 0; cc < 4; cc++) {
        int ch = chg*4 + cc;
        float s1 = 0.f, s2 = 0.f;
        float* o = out + (size_t)ch*RTOT + r0 + colg;
#pragma unroll
        for (int j = 0; j < 16; j++) {
            float v = acc[cc][j]; o[16*j] = v; s1 += v; s2 = fmaf(v, v, s2);
        }
        sr1[ch*16 + colg] = s1; sr2[ch*16 + colg] = s2;
    }
    __syncthreads();
    for (int ch = t; ch < COUT; ch += NT) {
        float a = 0.f, b2 = 0.f;
#pragma unroll
        for (int k = 0; k < 16; k++) { a += sr1[ch*16 + k]; b2 += sr2[ch*16 + k]; }
        part[((size_t)blockIdx.x*COUT + ch)*2]     = a;
        part[((size_t)blockIdx.x*COUT + ch)*2 + 1] = b2;
    }
}

// ---------------- Last conv: 64 -> 128, fused raw max over each 32-group ----
// Contiguous-16 column mapping: thread colg owns cols [colg*16, colg*16+16),
// entirely inside sample-group colg>>1, so group max = 15 fmax + 1 shfl_xor.
// relu+affine applied later (monotone since a>0), BN stats from partials.
__global__ __launch_bounds__(512, 1)
void conv_last_kernel(const float* __restrict__ in,
                      const float* __restrict__ A, const float* __restrict__ C,
                      const float* __restrict__ W, const float* __restrict__ B,
                      float* __restrict__ gmax,
                      float* __restrict__ part)
{
    extern __shared__ float sm[];
    float* ins = sm;                 // [64][256]
    float* ws  = sm + 64*256;        // [128][65]
    float* sr1 = ws + 128*65;        // [128][16]
    float* sr2 = sr1 + 128*16;
    const int NT = 512;
    int t = threadIdx.x; size_t r0 = (size_t)blockIdx.x * 256;

    for (int i = t; i < 128*64; i += NT) { int o = i >> 6, c = i & 63; ws[o*65 + c] = W[i]; }
    for (int i = t; i < 64*256; i += NT) {
        int c = i >> 8, col = i & 255;
        float v = fmaf(in[(size_t)c*RTOT + r0 + col], A[c], C[c]);
        ins[i] = fmaxf(v, 0.f);
    }
    __syncthreads();

    int colg = t & 15, chg = t >> 4;
    float acc[4][16];
#pragma unroll
    for (int cc = 0; cc < 4; cc++) {
        float bz = B[chg*4 + cc];
#pragma unroll
        for (int j = 0; j < 16; j++) acc[cc][j] = bz;
    }
    for (int c = 0; c < 64; c++) {
        const float4* xv4 = reinterpret_cast<const float4*>(ins + c*256 + colg*16);
        float4 v0 = xv4[0], v1 = xv4[1], v2 = xv4[2], v3 = xv4[3];
        float xv[16] = {v0.x,v0.y,v0.z,v0.w, v1.x,v1.y,v1.z,v1.w,
                        v2.x,v2.y,v2.z,v2.w, v3.x,v3.y,v3.z,v3.w};
#pragma unroll
        for (int cc = 0; cc < 4; cc++) {
            float wv = ws[(chg*4 + cc)*65 + c];
#pragma unroll
            for (int j = 0; j < 16; j++) acc[cc][j] = fmaf(wv, xv[j], acc[cc][j]);
        }
    }
#pragma unroll
    for (int cc = 0; cc < 4; cc++) {
        int ch = chg*4 + cc;
        float s1 = 0.f, s2 = 0.f;
        float m = acc[cc][0];
#pragma unroll
        for (int j = 0; j < 16; j++) {
            float v = acc[cc][j];
            s1 += v; s2 = fmaf(v, v, s2);
            m = fmaxf(m, v);
        }
        sr1[ch*16 + colg] = s1; sr2[ch*16 + colg] = s2;
        float om = __shfl_xor_sync(0xffffffffu, m, 1);   // partner = other half of group
        m = fmaxf(m, om);
        if ((colg & 1) == 0) {
            size_t grp = (size_t)blockIdx.x*8 + (colg >> 1);
            gmax[grp*128 + ch] = m;
        }
    }
    __syncthreads();
    for (int ch = t; ch < 128; ch += NT) {
        float a = 0.f, b2 = 0.f;
#pragma unroll
        for (int k = 0; k < 16; k++) { a += sr1[ch*16 + k]; b2 += sr2[ch*16 + k]; }
        part[((size_t)blockIdx.x*128 + ch)*2]     = a;
        part[((size_t)blockIdx.x*128 + ch)*2 + 1] = b2;
    }
}

// ---------------- Finalize: out = relu(a * rawmax + c) ----------------------
__global__ __launch_bounds__(256) void finalize_kernel(const float* __restrict__ gmax,
                                                       const float* __restrict__ A,
                                                       const float* __restrict__ C,
                                                       float* __restrict__ dout)
{
    int i = blockIdx.x * 256 + threadIdx.x;
    int ch = i & 127;
    dout[(size_t)BATCH*NPOINT*3 + i] = fmaxf(fmaf(gmax[i], A[ch], C[ch]), 0.f);
}

// ---------------- launch ----------------------------------------------------
extern "C" void kernel_launch(void* const* d_in, const int* in_sizes, int n_in,
                              void* d_out, int out_size)
{
    (void)in_sizes; (void)n_in; (void)out_size;
    const float* xyz = (const float*)d_in[0];
    const float* pts = (const float*)d_in[1];
    const float* w0  = (const float*)d_in[2];  const float* b0  = (const float*)d_in[3];
    const float* g0  = (const float*)d_in[4];  const float* be0 = (const float*)d_in[5];
    const float* w1  = (const float*)d_in[6];  const float* b1  = (const float*)d_in[7];
    const float* g1  = (const float*)d_in[8];  const float* be1 = (const float*)d_in[9];
    const float* w2  = (const float*)d_in[10]; const float* b2  = (const float*)d_in[11];
    const float* g2  = (const float*)d_in[12]; const float* be2 = (const float*)d_in[13];
    float* out = (float*)d_out;

    float *x0, *y0, *y1, *gmax, *part, *A0, *C0, *A1, *C1, *A2, *C2;
    cudaGetSymbolAddress((void**)&x0,   g_x0);
    cudaGetSymbolAddress((void**)&y0,   g_y0);
    cudaGetSymbolAddress((void**)&y1,   g_y1);
    cudaGetSymbolAddress((void**)&gmax, g_gmax);
    cudaGetSymbolAddress((void**)&part, g_part);
    cudaGetSymbolAddress((void**)&A0,   g_A0);  cudaGetSymbolAddress((void**)&C0, g_C0);
    cudaGetSymbolAddress((void**)&A1,   g_A1);  cudaGetSymbolAddress((void**)&C1, g_C1);
    cudaGetSymbolAddress((void**)&A2,   g_A2);  cudaGetSymbolAddress((void**)&C2, g_C2);

    const int C1_SMEM  = (64*256 + 64*65  + 64*16*2)  * 4;       // 90368
    const int C2_SMEM  = (64*256 + 128*65 + 128*16*2) * 4;       // 115200
    cudaFuncSetAttribute(conv_mid_kernel<64>, cudaFuncAttributeMaxDynamicSharedMemorySize, C1_SMEM);
    cudaFuncSetAttribute(conv_last_kernel,    cudaFuncAttributeMaxDynamicSharedMemorySize, C2_SMEM);

    fps_cluster_kernel<<<BATCH*FPB, 1024>>>(xyz, out);
    bq_kernel<<<BATCH*NPOINT/8, 256>>>(xyz, pts, out, x0);
    conv0_kernel<<<RTOT/256, 256>>>(x0, w0, b0, y0, part);
    stats_kernel<<<64, 256>>>(part, RTOT/256, 64, g0, be0, A0, C0);
    conv_mid_kernel<64><<<RTOT/256, 256, C1_SMEM>>>(y0, A0, C0, w1, b1, y1, part);
    stats_kernel<<<64, 256>>>(part, RTOT/256, 64, g1, be1, A1, C1);
    conv_last_kernel<<<RTOT/256, 512, C2_SMEM>>>(y1, A1, C1, w2, b2, gmax, part);
    stats_kernel<<<128, 256>>>(part, RTOT/256, 128, g2, be2, A2, C2);
    finalize_kernel<<<BATCH*NPOINT*128/256, 256>>>(gmax, A2, C2, out);
}

// round 9
// speedup vs baseline: 1.3203x; 1.2139x over previous
#include <cuda_runtime.h>
#include <math.h>
#include <stdint.h>

// Problem constants
#define BATCH   8
#define NPTS    16384
#define NPOINT  1024
#define NSAMP   32
#define RTOT    (BATCH*NPOINT*NSAMP)   /* 262144 rows */
#define FPB     8                      /* FPS CTAs per batch (cluster size) */
#define PPC     (NPTS/FPB)             /* 2048 points per CTA */

// ---------------- scratch (device globals; no allocations allowed) ----------
__device__ float g_x0[(size_t)RTOT*9];        // grouped+concat input  (9.4MB)
__device__ float g_y0[(size_t)64*RTOT];       // layer0 raw out [64][R] (67MB)
__device__ float g_y1[(size_t)64*RTOT];       // layer1 raw out (67MB)
__device__ float g_gmax[(size_t)BATCH*NPOINT*128]; // per-group raw max (4MB)
__device__ float g_part[(size_t)1024*128*2];  // per-block BN partial sums
__device__ float g_A0[64], g_C0[64];
__device__ float g_A1[64], g_C1[64];
__device__ float g_A2[128], g_C2[128];

__device__ __forceinline__ uint32_t s2u(const void* p) {
    return (uint32_t)__cvta_generic_to_shared(p);
}

__device__ __forceinline__ uint32_t mapa_rank(uint32_t a, uint32_t r) {
    uint32_t ra;
    asm volatile("mapa.shared::cluster.u32 %0, %1, %2;" : "=r"(ra) : "r"(a), "r"(r));
    return ra;
}

// spin on a LOCAL mbarrier with cluster-scope acquire (makes peer DSMEM
// stores released by the matching arrive visible)
__device__ __forceinline__ void mbar_wait_cluster(uint32_t a, uint32_t par) {
    uint32_t done = 0;
    do {
        asm volatile(
            "{\n\t.reg .pred p;\n\t"
            "mbarrier.try_wait.parity.acquire.cluster.shared::cta.b64 p, [%1], %2, 0x989680;\n\t"
            "selp.b32 %0, 1, 0, p;\n\t}"
            : "=r"(done) : "r"(a), "r"(par) : "memory");
    } while (!done);
}

__device__ __forceinline__ void mbar_arrive_cluster(uint32_t a) {
    asm volatile("mbarrier.arrive.release.cluster.shared::cluster.b64 _, [%0];"
                 :: "r"(a) : "memory");
}

// ---------------- FPS: 8-CTA cluster, mbarrier gather/broadcast tree --------
// Per iteration: per-thread update (2 pts in regs) -> warp redux argmax ->
// one __syncthreads -> warp0 redux over 32 warp records -> leader remote-
// stores {dist_bits,x,y,z} into CTA0 + arrive(gather mbar) -> CTA0 warp0
// selects winner (max dist, tie = lowest rank = lowest global index) ->
// lanes 0-7 push coords + arrive(each CTA's bcast mbar) -> everyone waits
// locally. Distance math identical to the passing version (bit-exact vs XLA);
// tie-break = lowest global index at every level.
__global__ __launch_bounds__(1024,1) __cluster_dims__(FPB,1,1)
void fps_cluster_kernel(const float* __restrict__ xyz, float* __restrict__ dout)
{
    __shared__ float sxl[PPC], syl[PPC], szl[PPC];
    __shared__ unsigned redK[32]; __shared__ int redI[32];
    __shared__ __align__(16) float gbuf[2][FPB][4];   // CTA0 gather slots {k,x,y,z}
    __shared__ __align__(16) float bbuf[2][4];        // local bcast slot {x,y,z}
    __shared__ __align__(8) unsigned long long mb_gather;  // used on CTA0
    __shared__ __align__(8) unsigned long long mb_bcast;

    int t = threadIdx.x;
    unsigned rank; asm("mov.u32 %0, %%cluster_ctarank;" : "=r"(rank));
    int b = blockIdx.x / FPB;
    const float* X = xyz + (size_t)b*NPTS*3;
    int base = (int)rank * PPC;

    int p0 = base + t, p1 = p0 + 1024;
    float x0v = X[3*p0], y0v = X[3*p0+1], z0v = X[3*p0+2];
    float x1v = X[3*p1], y1v = X[3*p1+1], z1v = X[3*p1+2];
    sxl[t]      = x0v; syl[t]      = y0v; szl[t]      = z0v;
    sxl[t+1024] = x1v; syl[t+1024] = y1v; szl[t+1024] = z1v;
    float d0 = 1e10f, d1 = 1e10f;
    float cx = X[0], cy = X[1], cz = X[2];   // deterministic start at index 0

    if (t == 0) {
        uint32_t mg = s2u(&mb_gather), mbc = s2u(&mb_bcast);
        asm volatile("mbarrier.init.shared.b64 [%0], %1;" :: "r"(mg),  "r"((uint32_t)FPB) : "memory");
        asm volatile("mbarrier.init.shared.b64 [%0], %1;" :: "r"(mbc), "r"(1u) : "memory");
    }
    __syncthreads();
    asm volatile("barrier.cluster.arrive.aligned;" ::: "memory");
    asm volatile("barrier.cluster.wait.aligned;"   ::: "memory");

    int lane = t & 31, w = t >> 5;
    // hoisted remote addresses
    uint32_t gdst0 = mapa_rank(s2u(&gbuf[0][rank][0]), 0);  // my slot in CTA0
    uint32_t gdst1 = mapa_rank(s2u(&gbuf[1][rank][0]), 0);
    uint32_t gmbar = mapa_rank(s2u(&mb_gather), 0);
    uint32_t pb0 = 0, pb1 = 0, pmb = 0;
    if (rank == 0 && w == 0 && lane < FPB) {                // bcast targets
        pb0 = mapa_rank(s2u(&bbuf[0][0]), (uint32_t)lane);
        pb1 = mapa_rank(s2u(&bbuf[1][0]), (uint32_t)lane);
        pmb = mapa_rank(s2u(&mb_bcast),   (uint32_t)lane);
    }
    uint32_t my_bcast = s2u(&mb_bcast);
    uint32_t my_gather = s2u(&mb_gather);
    float* co = dout + (size_t)b*NPOINT*3;

    for (int it = 0; it < NPOINT; it++) {
        if (rank == 0 && t == 0) { co[3*it] = cx; co[3*it+1] = cy; co[3*it+2] = cz; }

        // exact XLA lowering: sub, mul, add-add (no FMA contraction)
        float dx = __fsub_rn(x0v, cx), dy = __fsub_rn(y0v, cy), dz = __fsub_rn(z0v, cz);
        float d  = __fadd_rn(__fadd_rn(__fmul_rn(dx,dx), __fmul_rn(dy,dy)), __fmul_rn(dz,dz));
        d0 = fminf(d0, d);
        dx = __fsub_rn(x1v, cx); dy = __fsub_rn(y1v, cy); dz = __fsub_rn(z1v, cz);
        d  = __fadd_rn(__fadd_rn(__fmul_rn(dx,dx), __fmul_rn(dy,dy)), __fmul_rn(dz,dz));
        d1 = fminf(d1, d);

        float best = d0; int bi = p0;
        if (d1 > best) { best = d1; bi = p1; }   // strict >: lowest idx on ties

        // warp argmax: max dist bits (nonneg floats are bits-monotone),
        // tie -> min index
        unsigned kk = __float_as_uint(best);
        unsigned wm = __reduce_max_sync(0xffffffffu, kk);
        unsigned wbi = __reduce_min_sync(0xffffffffu,
                                         (kk == wm) ? (unsigned)bi : 0xffffffffu);
        if (lane == 0) { redK[w] = wm; redI[w] = (int)wbi; }
        __syncthreads();

        int par = it & 1;
        if (w == 0) {
            unsigned k2 = redK[lane]; int i2 = redI[lane];
            unsigned m2 = __reduce_max_sync(0xffffffffu, k2);
            unsigned wi = __reduce_min_sync(0xffffffffu,
                                            (k2 == m2) ? (unsigned)i2 : 0xffffffffu);
            if (lane == 0) {
                int loc = (int)wi - base;
                float lx = sxl[loc], ly = syl[loc], lz = szl[loc];
                uint32_t dst = par ? gdst1 : gdst0;
                asm volatile("st.shared::cluster.b32 [%0],    %1;" :: "r"(dst), "r"(m2) : "memory");
                asm volatile("st.shared::cluster.b32 [%0+4],  %1;" :: "r"(dst), "f"(lx) : "memory");
                asm volatile("st.shared::cluster.b32 [%0+8],  %1;" :: "r"(dst), "f"(ly) : "memory");
                asm volatile("st.shared::cluster.b32 [%0+12], %1;" :: "r"(dst), "f"(lz) : "memory");
                mbar_arrive_cluster(gmbar);
            }
            if (rank == 0) {
                mbar_wait_cluster(my_gather, (uint32_t)par);
                int r = lane & (FPB-1);
                unsigned kr = __float_as_uint(gbuf[par][r][0]);
                float xr = gbuf[par][r][1];
                float yr = gbuf[par][r][2];
                float zr = gbuf[par][r][3];
                unsigned mm = __reduce_max_sync(0xffffffffu, kr);
                unsigned msk = __ballot_sync(0xffffffffu, kr == mm);
                int wl = __ffs(msk) - 1;          // lowest lane = lowest rank = lowest idx
                float wx = __shfl_sync(0xffffffffu, xr, wl);
                float wy = __shfl_sync(0xffffffffu, yr, wl);
                float wz = __shfl_sync(0xffffffffu, zr, wl);
                if (lane < FPB) {
                    uint32_t bd = par ? pb1 : pb0;
                    asm volatile("st.shared::cluster.b32 [%0],   %1;" :: "r"(bd), "f"(wx) : "memory");
                    asm volatile("st.shared::cluster.b32 [%0+4], %1;" :: "r"(bd), "f"(wy) : "memory");
                    asm volatile("st.shared::cluster.b32 [%0+8], %1;" :: "r"(bd), "f"(wz) : "memory");
                    mbar_arrive_cluster(pmb);
                }
            }
        }
        mbar_wait_cluster(my_bcast, (uint32_t)par);
        cx = bbuf[par][0]; cy = bbuf[par][1]; cz = bbuf[par][2];
    }
    asm volatile("barrier.cluster.arrive.aligned;" ::: "memory");
    asm volatile("barrier.cluster.wait.aligned;"   ::: "memory");
}

// ---------------- Ball query + gather + concat: one warp per centroid -------
__global__ __launch_bounds__(256) void bq_kernel(const float* __restrict__ xyz,
                                                 const float* __restrict__ pts,
                                                 const float* __restrict__ cent,
                                                 float* __restrict__ x0)
{
    __shared__ int sbuf[8][NSAMP];
    int w = threadIdx.x >> 5, lane = threadIdx.x & 31;
    int wg = blockIdx.x * 8 + w;
    int b  = wg >> 10;
    const float* X = xyz + (size_t)b*NPTS*3;

    float cx = cent[3*wg], cy = cent[3*wg+1], cz = cent[3*wg+2];
    const float R2 = (float)(0.2*0.2);    // f32(0.04), NOT 0.2f*0.2f
    float sc = __fadd_rn(__fadd_rn(__fmul_rn(cx,cx), __fmul_rn(cy,cy)),
                         __fmul_rn(cz,cz));
    sbuf[w][lane] = 0;
    __syncwarp();

    int count = 0;
    for (int base = 0; base < NPTS; base += 32) {
        int p = base + lane;
        float x = X[3*p], y = X[3*p+1], z = X[3*p+2];
        float dot = __fadd_rn(__fadd_rn(__fmul_rn(cx,x), __fmul_rn(cy,y)),
                              __fmul_rn(cz,z));
        float sx2 = __fadd_rn(__fadd_rn(__fmul_rn(x,x), __fmul_rn(y,y)),
                              __fmul_rn(z,z));
        float d2  = __fadd_rn(__fsub_rn(sc, __fmul_rn(2.0f, dot)), sx2);
        bool in = d2 < R2;
        unsigned m = __ballot_sync(0xffffffffu, in);
        if (in) {
            int pos = count + __popc(m & ((1u << lane) - 1u));
            if (pos < NSAMP) sbuf[w][pos] = p;
        }
        count += __popc(m);
        if (count >= NSAMP) break;        // warp-uniform
    }
    __syncwarp();

    int idx = sbuf[w][lane];
    const float* PT = pts + (size_t)b*NPTS*6;
    float* o = x0 + ((size_t)wg*NSAMP + lane)*9;
    o[0] = __fsub_rn(X[3*idx],   cx);
    o[1] = __fsub_rn(X[3*idx+1], cy);
    o[2] = __fsub_rn(X[3*idx+2], cz);
#pragma unroll
    for (int k = 0; k < 6; k++) o[3+k] = PT[6*idx+k];
}

// ---------------- Layer 0: 9 -> 64, row-major in, channel-major out ---------
__global__ __launch_bounds__(256) void conv0_kernel(const float* __restrict__ x0,
                                                    const float* __restrict__ W,
                                                    const float* __restrict__ B,
                                                    float* __restrict__ y,
                                                    float* __restrict__ part)
{
    __shared__ float xs[256*9];
    __shared__ float sr1[4][64], sr2[4][64];
    int t = threadIdx.x; size_t r0 = (size_t)blockIdx.x * 256;
    for (int i = t; i < 256*9; i += 256) xs[i] = x0[r0*9 + i];

    int ch = t & 63, rg = t >> 6;
    float wv[9];
#pragma unroll
    for (int k = 0; k < 9; k++) wv[k] = W[ch*9 + k];
    float bias = B[ch];
    __syncthreads();

    float s1 = 0.f, s2 = 0.f;
    float* yo = y + (size_t)ch*RTOT + r0 + rg*64;
    const float* xr = xs + rg*64*9;
    for (int i = 0; i < 64; i++) {
        float acc = bias;
#pragma unroll
        for (int k = 0; k < 9; k++) acc = fmaf(wv[k], xr[i*9 + k], acc);
        yo[i] = acc; s1 += acc; s2 = fmaf(acc, acc, s2);
    }
    sr1[rg][ch] = s1; sr2[rg][ch] = s2;
    __syncthreads();
    if (rg == 0) {
        float a  = sr1[0][ch] + sr1[1][ch] + sr1[2][ch] + sr1[3][ch];
        float c2 = sr2[0][ch] + sr2[1][ch] + sr2[2][ch] + sr2[3][ch];
        part[((size_t)blockIdx.x*64 + ch)*2]     = a;
        part[((size_t)blockIdx.x*64 + ch)*2 + 1] = c2;
    }
}

// ---------------- BN stat finalize (deterministic, double accumulation) -----
__global__ __launch_bounds__(256) void stats_kernel(const float* __restrict__ part,
                                                    int nblk, int cout,
                                                    const float* __restrict__ g,
                                                    const float* __restrict__ be,
                                                    float* __restrict__ A,
                                                    float* __restrict__ C)
{
    __shared__ double r1[256], r2[256];
    int ch = blockIdx.x, t = threadIdx.x;
    double s1 = 0.0, s2 = 0.0;
    for (int i = t; i < nblk; i += 256) {
        const float* p = part + ((size_t)i*cout + ch)*2;
        s1 += (double)p[0]; s2 += (double)p[1];
    }
    r1[t] = s1; r2[t] = s2; __syncthreads();
    for (int o = 128; o > 0; o >>= 1) {
        if (t < o) { r1[t] += r1[t+o]; r2[t] += r2[t+o]; }
        __syncthreads();
    }
    if (t == 0) {
        double n = (double)RTOT;
        double mean = r1[0] / n;
        double var  = r2[0] / n - mean*mean;
        float rstd = (float)(1.0 / sqrt(var + 1e-5));
        float a = g[ch] * rstd;
        float c = be[ch] - (float)mean * a;
        A[ch] = a; C[ch] = c;
    }
}

// ---------------- Mid conv: 64 -> 64, prev-layer BN+ReLU fused on load ------
template<int COUT>
__global__ __launch_bounds__(COUT*4, 1)
void conv_mid_kernel(const float* __restrict__ in,
                     const float* __restrict__ A, const float* __restrict__ C,
                     const float* __restrict__ W, const float* __restrict__ B,
                     float* __restrict__ out,
                     float* __restrict__ part)
{
    extern __shared__ float sm[];
    float* ins = sm;                 // [64][256]
    float* ws  = sm + 64*256;        // [COUT][65] padded
    float* sr1 = ws + COUT*65;       // [COUT][16]
    float* sr2 = sr1 + COUT*16;
    const int NT = COUT*4;
    int t = threadIdx.x; size_t r0 = (size_t)blockIdx.x * 256;

    for (int i = t; i < COUT*64; i += NT) { int o = i >> 6, c = i & 63; ws[o*65 + c] = W[i]; }
    for (int i = t; i < 64*256; i += NT) {
        int c = i >> 8, col = i & 255;
        float v = fmaf(in[(size_t)c*RTOT + r0 + col], A[c], C[c]);
        ins[i] = fmaxf(v, 0.f);
    }
    __syncthreads();

    int colg = t & 15, chg = t >> 4;
    float acc[4][16];
#pragma unroll
    for (int cc = 0; cc < 4; cc++) {
        float bz = B[chg*4 + cc];
#pragma unroll
        for (int j = 0; j < 16; j++) acc[cc][j] = bz;
    }
    for (int c = 0; c < 64; c++) {
        float xv[16];
#pragma unroll
        for (int j = 0; j < 16; j++) xv[j] = ins[c*256 + colg + 16*j];
#pragma unroll
        for (int cc = 0; cc < 4; cc++) {
            float wv = ws[(chg*4 + cc)*65 + c];
#pragma unroll
            for (int j = 0; j < 16; j++) acc[cc][j] = fmaf(wv, xv[j], acc[cc][j]);
        }
    }
#pragma unroll
    for (int cc = 0; cc < 4; cc++) {
        int ch = chg*4 + cc;
        float s1 = 0.f, s2 = 0.f;
        float* o = out + (size_t)ch*RTOT + r0 + colg;
#pragma unroll
        for (int j = 0; j < 16; j++) {
            float v = acc[cc][j]; o[16*j] = v; s1 += v; s2 = fmaf(v, v, s2);
        }
        sr1[ch*16 + colg] = s1; sr2[ch*16 + colg] = s2;
    }
    __syncthreads();
    for (int ch = t; ch < COUT; ch += NT) {
        float a = 0.f, b2 = 0.f;
#pragma unroll
        for (int k = 0; k < 16; k++) { a += sr1[ch*16 + k]; b2 += sr2[ch*16 + k]; }
        part[((size_t)blockIdx.x*COUT + ch)*2]     = a;
        part[((size_t)blockIdx.x*COUT + ch)*2 + 1] = b2;
    }
}

// ---------------- Last conv: 64 -> 128, fused raw max over each 32-group ----
__global__ __launch_bounds__(512, 1)
void conv_last_kernel(const float* __restrict__ in,
                      const float* __restrict__ A, const float* __restrict__ C,
                      const float* __restrict__ W, const float* __restrict__ B,
                      float* __restrict__ gmax,
                      float* __restrict__ part)
{
    extern __shared__ float sm[];
    float* ins = sm;                 // [64][256]
    float* ws  = sm + 64*256;        // [128][65]
    float* sr1 = ws + 128*65;        // [128][16]
    float* sr2 = sr1 + 128*16;
    const int NT = 512;
    int t = threadIdx.x; size_t r0 = (size_t)blockIdx.x * 256;

    for (int i = t; i < 128*64; i += NT) { int o = i >> 6, c = i & 63; ws[o*65 + c] = W[i]; }
    for (int i = t; i < 64*256; i += NT) {
        int c = i >> 8, col = i & 255;
        float v = fmaf(in[(size_t)c*RTOT + r0 + col], A[c], C[c]);
        ins[i] = fmaxf(v, 0.f);
    }
    __syncthreads();

    int colg = t & 15, chg = t >> 4;
    float acc[4][16];
#pragma unroll
    for (int cc = 0; cc < 4; cc++) {
        float bz = B[chg*4 + cc];
#pragma unroll
        for (int j = 0; j < 16; j++) acc[cc][j] = bz;
    }
    for (int c = 0; c < 64; c++) {
        const float4* xv4 = reinterpret_cast<const float4*>(ins + c*256 + colg*16);
        float4 v0 = xv4[0], v1 = xv4[1], v2 = xv4[2], v3 = xv4[3];
        float xv[16] = {v0.x,v0.y,v0.z,v0.w, v1.x,v1.y,v1.z,v1.w,
                        v2.x,v2.y,v2.z,v2.w, v3.x,v3.y,v3.z,v3.w};
#pragma unroll
        for (int cc = 0; cc < 4; cc++) {
            float wv = ws[(chg*4 + cc)*65 + c];
#pragma unroll
            for (int j = 0; j < 16; j++) acc[cc][j] = fmaf(wv, xv[j], acc[cc][j]);
        }
    }
#pragma unroll
    for (int cc = 0; cc < 4; cc++) {
        int ch = chg*4 + cc;
        float s1 = 0.f, s2 = 0.f;
        float m = acc[cc][0];
#pragma unroll
        for (int j = 0; j < 16; j++) {
            float v = acc[cc][j];
            s1 += v; s2 = fmaf(v, v, s2);
            m = fmaxf(m, v);
        }
        sr1[ch*16 + colg] = s1; sr2[ch*16 + colg] = s2;
        float om = __shfl_xor_sync(0xffffffffu, m, 1);
        m = fmaxf(m, om);
        if ((colg & 1) == 0) {
            size_t grp = (size_t)blockIdx.x*8 + (colg >> 1);
            gmax[grp*128 + ch] = m;
        }
    }
    __syncthreads();
    for (int ch = t; ch < 128; ch += NT) {
        float a = 0.f, b2 = 0.f;
#pragma unroll
        for (int k = 0; k < 16; k++) { a += sr1[ch*16 + k]; b2 += sr2[ch*16 + k]; }
        part[((size_t)blockIdx.x*128 + ch)*2]     = a;
        part[((size_t)blockIdx.x*128 + ch)*2 + 1] = b2;
    }
}

// ---------------- Finalize: out = relu(a * rawmax + c) ----------------------
__global__ __launch_bounds__(256) void finalize_kernel(const float* __restrict__ gmax,
                                                       const float* __restrict__ A,
                                                       const float* __restrict__ C,
                                                       float* __restrict__ dout)
{
    int i = blockIdx.x * 256 + threadIdx.x;
    int ch = i & 127;
    dout[(size_t)BATCH*NPOINT*3 + i] = fmaxf(fmaf(gmax[i], A[ch], C[ch]), 0.f);
}

// ---------------- launch ----------------------------------------------------
extern "C" void kernel_launch(void* const* d_in, const int* in_sizes, int n_in,
                              void* d_out, int out_size)
{
    (void)in_sizes; (void)n_in; (void)out_size;
    const float* xyz = (const float*)d_in[0];
    const float* pts = (const float*)d_in[1];
    const float* w0  = (const float*)d_in[2];  const float* b0  = (const float*)d_in[3];
    const float* g0  = (const float*)d_in[4];  const float* be0 = (const float*)d_in[5];
    const float* w1  = (const float*)d_in[6];  const float* b1  = (const float*)d_in[7];
    const float* g1  = (const float*)d_in[8];  const float* be1 = (const float*)d_in[9];
    const float* w2  = (const float*)d_in[10]; const float* b2  = (const float*)d_in[11];
    const float* g2  = (const float*)d_in[12]; const float* be2 = (const float*)d_in[13];
    float* out = (float*)d_out;

    float *x0, *y0, *y1, *gmax, *part, *A0, *C0, *A1, *C1, *A2, *C2;
    cudaGetSymbolAddress((void**)&x0,   g_x0);
    cudaGetSymbolAddress((void**)&y0,   g_y0);
    cudaGetSymbolAddress((void**)&y1,   g_y1);
    cudaGetSymbolAddress((void**)&gmax, g_gmax);
    cudaGetSymbolAddress((void**)&part, g_part);
    cudaGetSymbolAddress((void**)&A0,   g_A0);  cudaGetSymbolAddress((void**)&C0, g_C0);
    cudaGetSymbolAddress((void**)&A1,   g_A1);  cudaGetSymbolAddress((void**)&C1, g_C1);
    cudaGetSymbolAddress((void**)&A2,   g_A2);  cudaGetSymbolAddress((void**)&C2, g_C2);

    const int C1_SMEM  = (64*256 + 64*65  + 64*16*2)  * 4;       // 90368
    const int C2_SMEM  = (64*256 + 128*65 + 128*16*2) * 4;       // 115200
    cudaFuncSetAttribute(conv_mid_kernel<64>, cudaFuncAttributeMaxDynamicSharedMemorySize, C1_SMEM);
    cudaFuncSetAttribute(conv_last_kernel,    cudaFuncAttributeMaxDynamicSharedMemorySize, C2_SMEM);

    fps_cluster_kernel<<<BATCH*FPB, 1024>>>(xyz, out);
    bq_kernel<<<BATCH*NPOINT/8, 256>>>(xyz, pts, out, x0);
    conv0_kernel<<<RTOT/256, 256>>>(x0, w0, b0, y0, part);
    stats_kernel<<<64, 256>>>(part, RTOT/256, 64, g0, be0, A0, C0);
    conv_mid_kernel<64><<<RTOT/256, 256, C1_SMEM>>>(y0, A0, C0, w1, b1, y1, part);
    stats_kernel<<<64, 256>>>(part, RTOT/256, 64, g1, be1, A1, C1);
    conv_last_kernel<<<RTOT/256, 512, C2_SMEM>>>(y1, A1, C1, w2, b2, gmax, part);
    stats_kernel<<<128, 256>>>(part, RTOT/256, 128, g2, be2, A2, C2);
    finalize_kernel<<<BATCH*NPOINT*128/256, 256>>>(gmax, A2, C2, out);
}

// round 13
// speedup vs baseline: 1.3654x; 1.0341x over previous
#include <cuda_runtime.h>
#include <math.h>
#include <stdint.h>

// Problem constants
#define BATCH   8
#define NPTS    16384
#define NPOINT  1024
#define NSAMP   32
#define RTOT    (BATCH*NPOINT*NSAMP)   /* 262144 rows */
#define FPB     8                      /* FPS CTAs per batch (cluster size) */
#define PPC     (NPTS/FPB)             /* 2048 points per CTA */

// ---------------- scratch (device globals; no allocations allowed) ----------
__device__ float g_x0[(size_t)RTOT*9];        // grouped+concat input  (9.4MB)
__device__ float g_y0[(size_t)64*RTOT];       // layer0 raw out [64][R] (67MB)
__device__ float g_y1[(size_t)64*RTOT];       // layer1 raw out (67MB)
__device__ float g_gmax[(size_t)BATCH*NPOINT*128]; // per-group raw max (4MB)
__device__ float g_part[(size_t)1024*128*2];  // per-block BN partial sums
__device__ float g_A0[64], g_C0[64];
__device__ float g_A1[64], g_C1[64];
__device__ float g_A2[128], g_C2[128];

__device__ __forceinline__ uint32_t s2u(const void* p) {
    return (uint32_t)__cvta_generic_to_shared(p);
}

__device__ __forceinline__ uint32_t mapa_rank(uint32_t a, uint32_t r) {
    uint32_t ra;
    asm volatile("mapa.shared::cluster.u32 %0, %1, %2;" : "=r"(ra) : "r"(a), "r"(r));
    return ra;
}

// spin on a LOCAL mbarrier with cluster-scope acquire (makes peer DSMEM
// stores released by the matching arrive visible)
__device__ __forceinline__ void mbar_wait_cluster(uint32_t a, uint32_t par) {
    uint32_t done = 0;
    do {
        asm volatile(
            "{\n\t.reg .pred p;\n\t"
            "mbarrier.try_wait.parity.acquire.cluster.shared::cta.b64 p, [%1], %2, 0x989680;\n\t"
            "selp.b32 %0, 1, 0, p;\n\t}"
            : "=r"(done) : "r"(a), "r"(par) : "memory");
    } while (!done);
}

__device__ __forceinline__ void mbar_arrive_cluster(uint32_t a) {
    asm volatile("mbarrier.arrive.release.cluster.shared::cluster.b64 _, [%0];"
                 :: "r"(a) : "memory");
}

// ---------------- FPS: 8-CTA cluster, all-to-all candidate broadcast --------
// Per iteration: per-thread update (2 pts in regs) -> warp redux argmax ->
// __syncthreads -> warp0 redux over 32 warp records -> lanes 0-7 each push
// the CTA record {dist_bits,x,y,z} into one peer CTA's slot + arrive at that
// peer's bcast mbarrier (count=8, parity double-buffered) -> single local
// wait -> every thread scans the 8 records in ascending rank with strict >.
// ONE DSMEM hop per iteration. Tie-break preserved at every level:
// within-CTA redux picks min index; across CTAs lowest rank = lowest global
// index range. Distance math identical to the passing version (bit-exact).
__global__ __launch_bounds__(1024,1) __cluster_dims__(FPB,1,1)
void fps_cluster_kernel(const float* __restrict__ xyz, float* __restrict__ dout)
{
    __shared__ float sxl[PPC], syl[PPC], szl[PPC];
    __shared__ unsigned redK[32]; __shared__ int redI[32];
    __shared__ __align__(16) float gbuf[2][FPB][4];   // [parity][src rank][{k,x,y,z}]
    __shared__ __align__(8) unsigned long long mb_bcast;

    int t = threadIdx.x;
    unsigned rank; asm("mov.u32 %0, %%cluster_ctarank;" : "=r"(rank));
    int b = blockIdx.x / FPB;
    const float* X = xyz + (size_t)b*NPTS*3;
    int base = (int)rank * PPC;

    int p0 = base + t, p1 = p0 + 1024;
    float x0v = X[3*p0], y0v = X[3*p0+1], z0v = X[3*p0+2];
    float x1v = X[3*p1], y1v = X[3*p1+1], z1v = X[3*p1+2];
    sxl[t]      = x0v; syl[t]      = y0v; szl[t]      = z0v;
    sxl[t+1024] = x1v; syl[t+1024] = y1v; szl[t+1024] = z1v;
    float d0 = 1e10f, d1 = 1e10f;
    float cx = X[0], cy = X[1], cz = X[2];   // deterministic start at index 0

    if (t == 0) {
        uint32_t mbc = s2u(&mb_bcast);
        asm volatile("mbarrier.init.shared.b64 [%0], %1;" :: "r"(mbc), "r"((uint32_t)FPB) : "memory");
    }
    __syncthreads();
    asm volatile("barrier.cluster.arrive.aligned;" ::: "memory");
    asm volatile("barrier.cluster.wait.aligned;"   ::: "memory");

    int lane = t & 31, w = t >> 5;
    // hoisted per-lane remote addresses (warp 0, lanes 0..7: one peer each)
    uint32_t pdst0 = 0, pdst1 = 0, pmb = 0;
    if (w == 0 && lane < FPB) {
        pdst0 = mapa_rank(s2u(&gbuf[0][rank][0]), (uint32_t)lane);
        pdst1 = mapa_rank(s2u(&gbuf[1][rank][0]), (uint32_t)lane);
        pmb   = mapa_rank(s2u(&mb_bcast),         (uint32_t)lane);
    }
    uint32_t my_bcast = s2u(&mb_bcast);
    float* co = dout + (size_t)b*NPOINT*3;

    for (int it = 0; it < NPOINT; it++) {
        if (rank == 0 && t == 0) { co[3*it] = cx; co[3*it+1] = cy; co[3*it+2] = cz; }

        // exact XLA lowering: sub, mul, add-add (no FMA contraction)
        float dx = __fsub_rn(x0v, cx), dy = __fsub_rn(y0v, cy), dz = __fsub_rn(z0v, cz);
        float d  = __fadd_rn(__fadd_rn(__fmul_rn(dx,dx), __fmul_rn(dy,dy)), __fmul_rn(dz,dz));
        d0 = fminf(d0, d);
        dx = __fsub_rn(x1v, cx); dy = __fsub_rn(y1v, cy); dz = __fsub_rn(z1v, cz);
        d  = __fadd_rn(__fadd_rn(__fmul_rn(dx,dx), __fmul_rn(dy,dy)), __fmul_rn(dz,dz));
        d1 = fminf(d1, d);

        float best = d0; int bi = p0;
        if (d1 > best) { best = d1; bi = p1; }   // strict >: lowest idx on ties

        // warp argmax: max dist bits (nonneg floats are bits-monotone),
        // tie -> min index
        unsigned kk = __float_as_uint(best);
        unsigned wm = __reduce_max_sync(0xffffffffu, kk);
        unsigned wbi = __reduce_min_sync(0xffffffffu,
                                         (kk == wm) ? (unsigned)bi : 0xffffffffu);
        if (lane == 0) { redK[w] = wm; redI[w] = (int)wbi; }
        __syncthreads();

        int par = it & 1;
        if (w == 0) {
            unsigned k2 = redK[lane]; int i2 = redI[lane];
            unsigned m2 = __reduce_max_sync(0xffffffffu, k2);
            unsigned wi = __reduce_min_sync(0xffffffffu,
                                            (k2 == m2) ? (unsigned)i2 : 0xffffffffu);
            if (lane < FPB) {
                int loc = (int)wi - base;            // uniform -> broadcast LDS
                float lx = sxl[loc], ly = syl[loc], lz = szl[loc];
                uint32_t dst = par ? pdst1 : pdst0;  // lane's peer CTA slot
                asm volatile("st.shared::cluster.b32 [%0],    %1;" :: "r"(dst), "r"(m2) : "memory");
                asm volatile("st.shared::cluster.b32 [%0+4],  %1;" :: "r"(dst), "f"(lx) : "memory");
                asm volatile("st.shared::cluster.b32 [%0+8],  %1;" :: "r"(dst), "f"(ly) : "memory");
                asm volatile("st.shared::cluster.b32 [%0+12], %1;" :: "r"(dst), "f"(lz) : "memory");
                mbar_arrive_cluster(pmb);
            }
        }
        // single local wait: 8 arrives (one per source CTA) flip the phase
        mbar_wait_cluster(my_bcast, (uint32_t)par);

        // scan 8 records in ascending rank; strict > keeps lowest rank on
        // ties == lowest global index (disjoint ordered ranges per rank)
        unsigned bk = __float_as_uint(gbuf[par][0][0]);
        int br = 0;
#pragma unroll
        for (int r = 1; r < FPB; r++) {
            unsigned kr = __float_as_uint(gbuf[par][r][0]);
            if (kr > bk) { bk = kr; br = r; }
        }
        cx = gbuf[par][br][1]; cy = gbuf[par][br][2]; cz = gbuf[par][br][3];
    }
    asm volatile("barrier.cluster.arrive.aligned;" ::: "memory");
    asm volatile("barrier.cluster.wait.aligned;"   ::: "memory");
}

// ---------------- Ball query + gather + concat: one warp per centroid -------
__global__ __launch_bounds__(256) void bq_kernel(const float* __restrict__ xyz,
                                                 const float* __restrict__ pts,
                                                 const float* __restrict__ cent,
                                                 float* __restrict__ x0)
{
    __shared__ int sbuf[8][NSAMP];
    int w = threadIdx.x >> 5, lane = threadIdx.x & 31;
    int wg = blockIdx.x * 8 + w;
    int b  = wg >> 10;
    const float* X = xyz + (size_t)b*NPTS*3;

    float cx = cent[3*wg], cy = cent[3*wg+1], cz = cent[3*wg+2];
    const float R2 = (float)(0.2*0.2);    // f32(0.04), NOT 0.2f*0.2f
    float sc = __fadd_rn(__fadd_rn(__fmul_rn(cx,cx), __fmul_rn(cy,cy)),
                         __fmul_rn(cz,cz));
    sbuf[w][lane] = 0;
    __syncwarp();

    int count = 0;
    for (int base = 0; base < NPTS; base += 32) {
        int p = base + lane;
        float x = X[3*p], y = X[3*p+1], z = X[3*p+2];
        float dot = __fadd_rn(__fadd_rn(__fmul_rn(cx,x), __fmul_rn(cy,y)),
                              __fmul_rn(cz,z));
        float sx2 = __fadd_rn(__fadd_rn(__fmul_rn(x,x), __fmul_rn(y,y)),
                              __fmul_rn(z,z));
        float d2  = __fadd_rn(__fsub_rn(sc, __fmul_rn(2.0f, dot)), sx2);
        bool in = d2 < R2;
        unsigned m = __ballot_sync(0xffffffffu, in);
        if (in) {
            int pos = count + __popc(m & ((1u << lane) - 1u));
            if (pos < NSAMP) sbuf[w][pos] = p;
        }
        count += __popc(m);
        if (count >= NSAMP) break;        // warp-uniform
    }
    __syncwarp();

    int idx = sbuf[w][lane];
    const float* PT = pts + (size_t)b*NPTS*6;
    float* o = x0 + ((size_t)wg*NSAMP + lane)*9;
    o[0] = __fsub_rn(X[3*idx],   cx);
    o[1] = __fsub_rn(X[3*idx+1], cy);
    o[2] = __fsub_rn(X[3*idx+2], cz);
#pragma unroll
    for (int k = 0; k < 6; k++) o[3+k] = PT[6*idx+k];
}

// ---------------- Layer 0: 9 -> 64, row-major in, channel-major out ---------
__global__ __launch_bounds__(256) void conv0_kernel(const float* __restrict__ x0,
                                                    const float* __restrict__ W,
                                                    const float* __restrict__ B,
                                                    float* __restrict__ y,
                                                    float* __restrict__ part)
{
    __shared__ float xs[256*9];
    __shared__ float sr1[4][64], sr2[4][64];
    int t = threadIdx.x; size_t r0 = (size_t)blockIdx.x * 256;
    for (int i = t; i < 256*9; i += 256) xs[i] = x0[r0*9 + i];

    int ch = t & 63, rg = t >> 6;
    float wv[9];
#pragma unroll
    for (int k = 0; k < 9; k++) wv[k] = W[ch*9 + k];
    float bias = B[ch];
    __syncthreads();

    float s1 = 0.f, s2 = 0.f;
    float* yo = y + (size_t)ch*RTOT + r0 + rg*64;
    const float* xr = xs + rg*64*9;
    for (int i = 0; i < 64; i++) {
        float acc = bias;
#pragma unroll
        for (int k = 0; k < 9; k++) acc = fmaf(wv[k], xr[i*9 + k], acc);
        yo[i] = acc; s1 += acc; s2 = fmaf(acc, acc, s2);
    }
    sr1[rg][ch] = s1; sr2[rg][ch] = s2;
    __syncthreads();
    if (rg == 0) {
        float a  = sr1[0][ch] + sr1[1][ch] + sr1[2][ch] + sr1[3][ch];
        float c2 = sr2[0][ch] + sr2[1][ch] + sr2[2][ch] + sr2[3][ch];
        part[((size_t)blockIdx.x*64 + ch)*2]     = a;
        part[((size_t)blockIdx.x*64 + ch)*2 + 1] = c2;
    }
}

// ---------------- BN stat finalize (deterministic, double accumulation) -----
__global__ __launch_bounds__(256) void stats_kernel(const float* __restrict__ part,
                                                    int nblk, int cout,
                                                    const float* __restrict__ g,
                                                    const float* __restrict__ be,
                                                    float* __restrict__ A,
                                                    float* __restrict__ C)
{
    __shared__ double r1[256], r2[256];
    int ch = blockIdx.x, t = threadIdx.x;
    double s1 = 0.0, s2 = 0.0;
    for (int i = t; i < nblk; i += 256) {
        const float* p = part + ((size_t)i*cout + ch)*2;
        s1 += (double)p[0]; s2 += (double)p[1];
    }
    r1[t] = s1; r2[t] = s2; __syncthreads();
    for (int o = 128; o > 0; o >>= 1) {
        if (t < o) { r1[t] += r1[t+o]; r2[t] += r2[t+o]; }
        __syncthreads();
    }
    if (t == 0) {
        double n = (double)RTOT;
        double mean = r1[0] / n;
        double var  = r2[0] / n - mean*mean;
        float rstd = (float)(1.0 / sqrt(var + 1e-5));
        float a = g[ch] * rstd;
        float c = be[ch] - (float)mean * a;
        A[ch] = a; C[ch] = c;
    }
}

// ---------------- Mid conv: 64 -> 64, prev-layer BN+ReLU fused on load ------
template<int COUT>
__global__ __launch_bounds__(COUT*4, 1)
void conv_mid_kernel(const float* __restrict__ in,
                     const float* __restrict__ A, const float* __restrict__ C,
                     const float* __restrict__ W, const float* __restrict__ B,
                     float* __restrict__ out,
                     float* __restrict__ part)
{
    extern __shared__ float sm[];
    float* ins = sm;                 // [64][256]
    float* ws  = sm + 64*256;        // [COUT][65] padded
    float* sr1 = ws + COUT*65;       // [COUT][16]
    float* sr2 = sr1 + COUT*16;
    const int NT = COUT*4;
    int t = threadIdx.x; size_t r0 = (size_t)blockIdx.x * 256;

    for (int i = t; i < COUT*64; i += NT) { int o = i >> 6, c = i & 63; ws[o*65 + c] = W[i]; }
    for (int i = t; i < 64*256; i += NT) {
        int c = i >> 8, col = i & 255;
        float v = fmaf(in[(size_t)c*RTOT + r0 + col], A[c], C[c]);
        ins[i] = fmaxf(v, 0.f);
    }
    __syncthreads();

    int colg = t & 15, chg = t >> 4;
    float acc[4][16];
#pragma unroll
    for (int cc = 0; cc < 4; cc++) {
        float bz = B[chg*4 + cc];
#pragma unroll
        for (int j = 0; j < 16; j++) acc[cc][j] = bz;
    }
    for (int c = 0; c < 64; c++) {
        float xv[16];
#pragma unroll
        for (int j = 0; j < 16; j++) xv[j] = ins[c*256 + colg + 16*j];
#pragma unroll
        for (int cc = 0; cc < 4; cc++) {
            float wv = ws[(chg*4 + cc)*65 + c];
#pragma unroll
            for (int j = 0; j < 16; j++) acc[cc][j] = fmaf(wv, xv[j], acc[cc][j]);
        }
    }
#pragma unroll
    for (int cc = 0; cc < 4; cc++) {
        int ch = chg*4 + cc;
        float s1 = 0.f, s2 = 0.f;
        float* o = out + (size_t)ch*RTOT + r0 + colg;
#pragma unroll
        for (int j = 0; j < 16; j++) {
            float v = acc[cc][j]; o[16*j] = v; s1 += v; s2 = fmaf(v, v, s2);
        }
        sr1[ch*16 + colg] = s1; sr2[ch*16 + colg] = s2;
    }
    __syncthreads();
    for (int ch = t; ch < COUT; ch += NT) {
        float a = 0.f, b2 = 0.f;
#pragma unroll
        for (int k = 0; k < 16; k++) { a += sr1[ch*16 + k]; b2 += sr2[ch*16 + k]; }
        part[((size_t)blockIdx.x*COUT + ch)*2]     = a;
        part[((size_t)blockIdx.x*COUT + ch)*2 + 1] = b2;
    }
}

// ---------------- Last conv: 64 -> 128, fused raw max over each 32-group ----
__global__ __launch_bounds__(512, 1)
void conv_last_kernel(const float* __restrict__ in,
                      const float* __restrict__ A, const float* __restrict__ C,
                      const float* __restrict__ W, const float* __restrict__ B,
                      float* __restrict__ gmax,
                      float* __restrict__ part)
{
    extern __shared__ float sm[];
    float* ins = sm;                 // [64][256]
    float* ws  = sm + 64*256;        // [128][65]
    float* sr1 = ws + 128*65;        // [128][16]
    float* sr2 = sr1 + 128*16;
    const int NT = 512;
    int t = threadIdx.x; size_t r0 = (size_t)blockIdx.x * 256;

    for (int i = t; i < 128*64; i += NT) { int o = i >> 6, c = i & 63; ws[o*65 + c] = W[i]; }
    for (int i = t; i < 64*256; i += NT) {
        int c = i >> 8, col = i & 255;
        float v = fmaf(in[(size_t)c*RTOT + r0 + col], A[c], C[c]);
        ins[i] = fmaxf(v, 0.f);
    }
    __syncthreads();

    int colg = t & 15, chg = t >> 4;
    float acc[4][16];
#pragma unroll
    for (int cc = 0; cc < 4; cc++) {
        float bz = B[chg*4 + cc];
#pragma unroll
        for (int j = 0; j < 16; j++) acc[cc][j] = bz;
    }
    for (int c = 0; c < 64; c++) {
        const float4* xv4 = reinterpret_cast<const float4*>(ins + c*256 + colg*16);
        float4 v0 = xv4[0], v1 = xv4[1], v2 = xv4[2], v3 = xv4[3];
        float xv[16] = {v0.x,v0.y,v0.z,v0.w, v1.x,v1.y,v1.z,v1.w,
                        v2.x,v2.y,v2.z,v2.w, v3.x,v3.y,v3.z,v3.w};
#pragma unroll
        for (int cc = 0; cc < 4; cc++) {
            float wv = ws[(chg*4 + cc)*65 + c];
#pragma unroll
            for (int j = 0; j < 16; j++) acc[cc][j] = fmaf(wv, xv[j], acc[cc][j]);
        }
    }
#pragma unroll
    for (int cc = 0; cc < 4; cc++) {
        int ch = chg*4 + cc;
        float s1 = 0.f, s2 = 0.f;
        float m = acc[cc][0];
#pragma unroll
        for (int j = 0; j < 16; j++) {
            float v = acc[cc][j];
            s1 += v; s2 = fmaf(v, v, s2);
            m = fmaxf(m, v);
        }
        sr1[ch*16 + colg] = s1; sr2[ch*16 + colg] = s2;
        float om = __shfl_xor_sync(0xffffffffu, m, 1);
        m = fmaxf(m, om);
        if ((colg & 1) == 0) {
            size_t grp = (size_t)blockIdx.x*8 + (colg >> 1);
            gmax[grp*128 + ch] = m;
        }
    }
    __syncthreads();
    for (int ch = t; ch < 128; ch += NT) {
        float a = 0.f, b2 = 0.f;
#pragma unroll
        for (int k = 0; k < 16; k++) { a += sr1[ch*16 + k]; b2 += sr2[ch*16 + k]; }
        part[((size_t)blockIdx.x*128 + ch)*2]     = a;
        part[((size_t)blockIdx.x*128 + ch)*2 + 1] = b2;
    }
}

// ---------------- Finalize: out = relu(a * rawmax + c) ----------------------
__global__ __launch_bounds__(256) void finalize_kernel(const float* __restrict__ gmax,
                                                       const float* __restrict__ A,
                                                       const float* __restrict__ C,
                                                       float* __restrict__ dout)
{
    int i = blockIdx.x * 256 + threadIdx.x;
    int ch = i & 127;
    dout[(size_t)BATCH*NPOINT*3 + i] = fmaxf(fmaf(gmax[i], A[ch], C[ch]), 0.f);
}

// ---------------- launch ----------------------------------------------------
extern "C" void kernel_launch(void* const* d_in, const int* in_sizes, int n_in,
                              void* d_out, int out_size)
{
    (void)in_sizes; (void)n_in; (void)out_size;
    const float* xyz = (const float*)d_in[0];
    const float* pts = (const float*)d_in[1];
    const float* w0  = (const float*)d_in[2];  const float* b0  = (const float*)d_in[3];
    const float* g0  = (const float*)d_in[4];  const float* be0 = (const float*)d_in[5];
    const float* w1  = (const float*)d_in[6];  const float* b1  = (const float*)d_in[7];
    const float* g1  = (const float*)d_in[8];  const float* be1 = (const float*)d_in[9];
    const float* w2  = (const float*)d_in[10]; const float* b2  = (const float*)d_in[11];
    const float* g2  = (const float*)d_in[12]; const float* be2 = (const float*)d_in[13];
    float* out = (float*)d_out;

    float *x0, *y0, *y1, *gmax, *part, *A0, *C0, *A1, *C1, *A2, *C2;
    cudaGetSymbolAddress((void**)&x0,   g_x0);
    cudaGetSymbolAddress((void**)&y0,   g_y0);
    cudaGetSymbolAddress((void**)&y1,   g_y1);
    cudaGetSymbolAddress((void**)&gmax, g_gmax);
    cudaGetSymbolAddress((void**)&part, g_part);
    cudaGetSymbolAddress((void**)&A0,   g_A0);  cudaGetSymbolAddress((void**)&C0, g_C0);
    cudaGetSymbolAddress((void**)&A1,   g_A1);  cudaGetSymbolAddress((void**)&C1, g_C1);
    cudaGetSymbolAddress((void**)&A2,   g_A2);  cudaGetSymbolAddress((void**)&C2, g_C2);

    const int C1_SMEM  = (64*256 + 64*65  + 64*16*2)  * 4;       // 90368
    const int C2_SMEM  = (64*256 + 128*65 + 128*16*2) * 4;       // 115200
    cudaFuncSetAttribute(conv_mid_kernel<64>, cudaFuncAttributeMaxDynamicSharedMemorySize, C1_SMEM);
    cudaFuncSetAttribute(conv_last_kernel,    cudaFuncAttributeMaxDynamicSharedMemorySize, C2_SMEM);

    fps_cluster_kernel<<<BATCH*FPB, 1024>>>(xyz, out);
    bq_kernel<<<BATCH*NPOINT/8, 256>>>(xyz, pts, out, x0);
    conv0_kernel<<<RTOT/256, 256>>>(x0, w0, b0, y0, part);
    stats_kernel<<<64, 256>>>(part, RTOT/256, 64, g0, be0, A0, C0);
    conv_mid_kernel<64><<<RTOT/256, 256, C1_SMEM>>>(y0, A0, C0, w1, b1, y1, part);
    stats_kernel<<<64, 256>>>(part, RTOT/256, 64, g1, be1, A1, C1);
    conv_last_kernel<<<RTOT/256, 512, C2_SMEM>>>(y1, A1, C1, w2, b2, gmax, part);
    stats_kernel<<<128, 256>>>(part, RTOT/256, 128, g2, be2, A2, C2);
    finalize_kernel<<<BATCH*NPOINT*128/256, 256>>>(gmax, A2, C2, out);
}

// round 14
// speedup vs baseline: 1.6223x; 1.1882x over previous
#include <cuda_runtime.h>
#include <math.h>
#include <stdint.h>

// Problem constants
#define BATCH   8
#define NPTS    16384
#define NPOINT  1024
#define NSAMP   32
#define RTOT    (BATCH*NPOINT*NSAMP)   /* 262144 rows */
#define FPB     8                      /* FPS CTAs per batch (cluster size) */
#define PPC     (NPTS/FPB)             /* 2048 points per CTA */
#define FTH     256                    /* FPS threads per CTA */
#define PPT     (PPC/FTH)              /* 8 points per thread */

// ---------------- scratch (device globals; no allocations allowed) ----------
__device__ float g_x0[(size_t)RTOT*9];        // grouped+concat input  (9.4MB)
__device__ float g_y0[(size_t)64*RTOT];       // layer0 raw out [64][R] (67MB)
__device__ float g_y1[(size_t)64*RTOT];       // layer1 raw out (67MB)
__device__ float g_gmax[(size_t)BATCH*NPOINT*128]; // per-group raw max (4MB)
__device__ float g_part[(size_t)1024*128*2];  // per-block BN partial sums
__device__ float g_A0[64], g_C0[64];
__device__ float g_A1[64], g_C1[64];
__device__ float g_A2[128], g_C2[128];

__device__ __forceinline__ uint32_t s2u(const void* p) {
    return (uint32_t)__cvta_generic_to_shared(p);
}

__device__ __forceinline__ uint32_t mapa_rank(uint32_t a, uint32_t r) {
    uint32_t ra;
    asm volatile("mapa.shared::cluster.u32 %0, %1, %2;" : "=r"(ra) : "r"(a), "r"(r));
    return ra;
}

// spin on a LOCAL mbarrier with cluster-scope acquire (makes peer DSMEM
// stores released by the matching arrive visible)
__device__ __forceinline__ void mbar_wait_cluster(uint32_t a, uint32_t par) {
    uint32_t done = 0;
    do {
        asm volatile(
            "{\n\t.reg .pred p;\n\t"
            "mbarrier.try_wait.parity.acquire.cluster.shared::cta.b64 p, [%1], %2, 0x989680;\n\t"
            "selp.b32 %0, 1, 0, p;\n\t}"
            : "=r"(done) : "r"(a), "r"(par) : "memory");
    } while (!done);
}

__device__ __forceinline__ void mbar_arrive_cluster(uint32_t a) {
    asm volatile("mbarrier.arrive.release.cluster.shared::cluster.b64 _, [%0];"
                 :: "r"(a) : "memory");
}

// ---------------- dummy: shifts ncu's -s 5 -c 1 window onto fps -------------
__global__ void noop_kernel() {}

// ---------------- FPS: 8-CTA cluster, 256 thr x 8 reg-resident points -------
// Per iteration: per-thread update of 8 points (registers) -> warp redux
// argmax -> __syncthreads (8 warps) -> warp0 redux over 8 warp records ->
// lanes 0-7 push the CTA record {dist_bits,x,y,z} into one peer CTA's slot +
// arrive at that peer's bcast mbarrier (count=8, parity double-buffered) ->
// single local wait -> every thread scans the 8 records in ascending rank
// with strict >. Tie-break preserved at every level: ascending-k strict >
// keeps lowest local index; redux pair keeps min index; lowest rank = lowest
// global index range. Distance math identical to the passing version
// (bit-exact vs XLA) -> trajectory unchanged.
__global__ __launch_bounds__(FTH,1) __cluster_dims__(FPB,1,1)
void fps_cluster_kernel(const float* __restrict__ xyz, float* __restrict__ dout)
{
    __shared__ float sxl[PPC], syl[PPC], szl[PPC];
    __shared__ unsigned redK[8]; __shared__ int redI[8];
    __shared__ __align__(16) float gbuf[2][FPB][4];   // [parity][src rank][{k,x,y,z}]
    __shared__ __align__(8) unsigned long long mb_bcast;

    int t = threadIdx.x;
    unsigned rank; asm("mov.u32 %0, %%cluster_ctarank;" : "=r"(rank));
    int b = blockIdx.x / FPB;
    const float* X = xyz + (size_t)b*NPTS*3;
    int base = (int)rank * PPC;

    float px[PPT], py[PPT], pz[PPT], pd[PPT];
#pragma unroll
    for (int k = 0; k < PPT; k++) {
        int li = t + k*FTH;               // local index, ascending in k
        int gp = base + li;
        px[k] = X[3*gp]; py[k] = X[3*gp+1]; pz[k] = X[3*gp+2];
        sxl[li] = px[k]; syl[li] = py[k]; szl[li] = pz[k];
        pd[k] = 1e10f;
    }
    float cx = X[0], cy = X[1], cz = X[2];   // deterministic start at index 0

    if (t == 0) {
        uint32_t mbc = s2u(&mb_bcast);
        asm volatile("mbarrier.init.shared.b64 [%0], %1;" :: "r"(mbc), "r"((uint32_t)FPB) : "memory");
    }
    __syncthreads();
    asm volatile("barrier.cluster.arrive.aligned;" ::: "memory");
    asm volatile("barrier.cluster.wait.aligned;"   ::: "memory");

    int lane = t & 31, w = t >> 5;
    // hoisted per-lane remote addresses (warp 0, lanes 0..7: one peer each)
    uint32_t pdst0 = 0, pdst1 = 0, pmb = 0;
    if (w == 0 && lane < FPB) {
        pdst0 = mapa_rank(s2u(&gbuf[0][rank][0]), (uint32_t)lane);
        pdst1 = mapa_rank(s2u(&gbuf[1][rank][0]), (uint32_t)lane);
        pmb   = mapa_rank(s2u(&mb_bcast),         (uint32_t)lane);
    }
    uint32_t my_bcast = s2u(&mb_bcast);
    float* co = dout + (size_t)b*NPOINT*3;

    for (int it = 0; it < NPOINT; it++) {
        if (rank == 0 && t == 0) { co[3*it] = cx; co[3*it+1] = cy; co[3*it+2] = cz; }

        // exact XLA lowering per point: sub, mul, add-add (no FMA contraction)
        float best = -1.0f; int bi = 0;
#pragma unroll
        for (int k = 0; k < PPT; k++) {
            float dx = __fsub_rn(px[k], cx);
            float dy = __fsub_rn(py[k], cy);
            float dz = __fsub_rn(pz[k], cz);
            float d  = __fadd_rn(__fadd_rn(__fmul_rn(dx,dx), __fmul_rn(dy,dy)),
                                 __fmul_rn(dz,dz));
            float nd = fminf(pd[k], d);
            pd[k] = nd;
            if (nd > best) { best = nd; bi = t + k*FTH; }  // strict >: lowest li
        }

        // warp argmax: max dist bits (nonneg floats bits-monotone), tie -> min idx
        unsigned kk = __float_as_uint(best);
        unsigned wm = __reduce_max_sync(0xffffffffu, kk);
        unsigned wbi = __reduce_min_sync(0xffffffffu,
                                         (kk == wm) ? (unsigned)bi : 0xffffffffu);
        if (lane == 0) { redK[w] = wm; redI[w] = (int)wbi; }
        __syncthreads();

        int par = it & 1;
        if (w == 0) {
            unsigned k2 = (lane < 8) ? redK[lane] : 0u;
            unsigned i2 = (lane < 8) ? (unsigned)redI[lane] : 0xffffffffu;
            unsigned m2 = __reduce_max_sync(0xffffffffu, k2);
            unsigned wi = __reduce_min_sync(0xffffffffu,
                                            (k2 == m2) ? i2 : 0xffffffffu);
            if (lane < FPB) {
                int loc = (int)wi;                   // uniform -> broadcast LDS
                float lx = sxl[loc], ly = syl[loc], lz = szl[loc];
                uint32_t dst = par ? pdst1 : pdst0;  // lane's peer CTA slot
                asm volatile("st.shared::cluster.b32 [%0],    %1;" :: "r"(dst), "r"(m2) : "memory");
                asm volatile("st.shared::cluster.b32 [%0+4],  %1;" :: "r"(dst), "f"(lx) : "memory");
                asm volatile("st.shared::cluster.b32 [%0+8],  %1;" :: "r"(dst), "f"(ly) : "memory");
                asm volatile("st.shared::cluster.b32 [%0+12], %1;" :: "r"(dst), "f"(lz) : "memory");
                mbar_arrive_cluster(pmb);
            }
        }
        // single local wait: 8 arrives (one per source CTA) flip the phase
        mbar_wait_cluster(my_bcast, (uint32_t)par);

        // scan 8 records in ascending rank; strict > keeps lowest rank on
        // ties == lowest global index (disjoint ordered ranges per rank)
        unsigned bk = __float_as_uint(gbuf[par][0][0]);
        int br = 0;
#pragma unroll
        for (int r = 1; r < FPB; r++) {
            unsigned kr = __float_as_uint(gbuf[par][r][0]);
            if (kr > bk) { bk = kr; br = r; }
        }
        cx = gbuf[par][br][1]; cy = gbuf[par][br][2]; cz = gbuf[par][br][3];
    }
    asm volatile("barrier.cluster.arrive.aligned;" ::: "memory");
    asm volatile("barrier.cluster.wait.aligned;"   ::: "memory");
}

// ---------------- Ball query + gather + concat: one warp per centroid -------
__global__ __launch_bounds__(256) void bq_kernel(const float* __restrict__ xyz,
                                                 const float* __restrict__ pts,
                                                 const float* __restrict__ cent,
                                                 float* __restrict__ x0)
{
    __shared__ int sbuf[8][NSAMP];
    int w = threadIdx.x >> 5, lane = threadIdx.x & 31;
    int wg = blockIdx.x * 8 + w;
    int b  = wg >> 10;
    const float* X = xyz + (size_t)b*NPTS*3;

    float cx = cent[3*wg], cy = cent[3*wg+1], cz = cent[3*wg+2];
    const float R2 = (float)(0.2*0.2);    // f32(0.04), NOT 0.2f*0.2f
    float sc = __fadd_rn(__fadd_rn(__fmul_rn(cx,cx), __fmul_rn(cy,cy)),
                         __fmul_rn(cz,cz));
    sbuf[w][lane] = 0;
    __syncwarp();

    int count = 0;
    for (int base = 0; base < NPTS; base += 32) {
        int p = base + lane;
        float x = X[3*p], y = X[3*p+1], z = X[3*p+2];
        float dot = __fadd_rn(__fadd_rn(__fmul_rn(cx,x), __fmul_rn(cy,y)),
                              __fmul_rn(cz,z));
        float sx2 = __fadd_rn(__fadd_rn(__fmul_rn(x,x), __fmul_rn(y,y)),
                              __fmul_rn(z,z));
        float d2  = __fadd_rn(__fsub_rn(sc, __fmul_rn(2.0f, dot)), sx2);
        bool in = d2 < R2;
        unsigned m = __ballot_sync(0xffffffffu, in);
        if (in) {
            int pos = count + __popc(m & ((1u << lane) - 1u));
            if (pos < NSAMP) sbuf[w][pos] = p;
        }
        count += __popc(m);
        if (count >= NSAMP) break;        // warp-uniform
    }
    __syncwarp();

    int idx = sbuf[w][lane];
    const float* PT = pts + (size_t)b*NPTS*6;
    float* o = x0 + ((size_t)wg*NSAMP + lane)*9;
    o[0] = __fsub_rn(X[3*idx],   cx);
    o[1] = __fsub_rn(X[3*idx+1], cy);
    o[2] = __fsub_rn(X[3*idx+2], cz);
#pragma unroll
    for (int k = 0; k < 6; k++) o[3+k] = PT[6*idx+k];
}

// ---------------- Layer 0: 9 -> 64, row-major in, channel-major out ---------
__global__ __launch_bounds__(256) void conv0_kernel(const float* __restrict__ x0,
                                                    const float* __restrict__ W,
                                                    const float* __restrict__ B,
                                                    float* __restrict__ y,
                                                    float* __restrict__ part)
{
    __shared__ float xs[256*9];
    __shared__ float sr1[4][64], sr2[4][64];
    int t = threadIdx.x; size_t r0 = (size_t)blockIdx.x * 256;
    for (int i = t; i < 256*9; i += 256) xs[i] = x0[r0*9 + i];

    int ch = t & 63, rg = t >> 6;
    float wv[9];
#pragma unroll
    for (int k = 0; k < 9; k++) wv[k] = W[ch*9 + k];
    float bias = B[ch];
    __syncthreads();

    float s1 = 0.f, s2 = 0.f;
    float* yo = y + (size_t)ch*RTOT + r0 + rg*64;
    const float* xr = xs + rg*64*9;
    for (int i = 0; i < 64; i++) {
        float acc = bias;
#pragma unroll
        for (int k = 0; k < 9; k++) acc = fmaf(wv[k], xr[i*9 + k], acc);
        yo[i] = acc; s1 += acc; s2 = fmaf(acc, acc, s2);
    }
    sr1[rg][ch] = s1; sr2[rg][ch] = s2;
    __syncthreads();
    if (rg == 0) {
        float a  = sr1[0][ch] + sr1[1][ch] + sr1[2][ch] + sr1[3][ch];
        float c2 = sr2[0][ch] + sr2[1][ch] + sr2[2][ch] + sr2[3][ch];
        part[((size_t)blockIdx.x*64 + ch)*2]     = a;
        part[((size_t)blockIdx.x*64 + ch)*2 + 1] = c2;
    }
}

// ---------------- BN stat finalize (deterministic, double accumulation) -----
__global__ __launch_bounds__(256) void stats_kernel(const float* __restrict__ part,
                                                    int nblk, int cout,
                                                    const float* __restrict__ g,
                                                    const float* __restrict__ be,
                                                    float* __restrict__ A,
                                                    float* __restrict__ C)
{
    __shared__ double r1[256], r2[256];
    int ch = blockIdx.x, t = threadIdx.x;
    double s1 = 0.0, s2 = 0.0;
    for (int i = t; i < nblk; i += 256) {
        const float* p = part + ((size_t)i*cout + ch)*2;
        s1 += (double)p[0]; s2 += (double)p[1];
    }
    r1[t] = s1; r2[t] = s2; __syncthreads();
    for (int o = 128; o > 0; o >>= 1) {
        if (t < o) { r1[t] += r1[t+o]; r2[t] += r2[t+o]; }
        __syncthreads();
    }
    if (t == 0) {
        double n = (double)RTOT;
        double mean = r1[0] / n;
        double var  = r2[0] / n - mean*mean;
        float rstd = (float)(1.0 / sqrt(var + 1e-5));
        float a = g[ch] * rstd;
        float c = be[ch] - (float)mean * a;
        A[ch] = a; C[ch] = c;
    }
}

// ---------------- Mid conv: 64 -> 64, prev-layer BN+ReLU fused on load ------
template<int COUT>
__global__ __launch_bounds__(COUT*4, 1)
void conv_mid_kernel(const float* __restrict__ in,
                     const float* __restrict__ A, const float* __restrict__ C,
                     const float* __restrict__ W, const float* __restrict__ B,
                     float* __restrict__ out,
                     float* __restrict__ part)
{
    extern __shared__ float sm[];
    float* ins = sm;                 // [64][256]
    float* ws  = sm + 64*256;        // [COUT][65] padded
    float* sr1 = ws + COUT*65;       // [COUT][16]
    float* sr2 = sr1 + COUT*16;
    const int NT = COUT*4;
    int t = threadIdx.x; size_t r0 = (size_t)blockIdx.x * 256;

    for (int i = t; i < COUT*64; i += NT) { int o = i >> 6, c = i & 63; ws[o*65 + c] = W[i]; }
    for (int i = t; i < 64*256; i += NT) {
        int c = i >> 8, col = i & 255;
        float v = fmaf(in[(size_t)c*RTOT + r0 + col], A[c], C[c]);
        ins[i] = fmaxf(v, 0.f);
    }
    __syncthreads();

    int colg = t & 15, chg = t >> 4;
    float acc[4][16];
#pragma unroll
    for (int cc = 0; cc < 4; cc++) {
        float bz = B[chg*4 + cc];
#pragma unroll
        for (int j = 0; j < 16; j++) acc[cc][j] = bz;
    }
    for (int c = 0; c < 64; c++) {
        float xv[16];
#pragma unroll
        for (int j = 0; j < 16; j++) xv[j] = ins[c*256 + colg + 16*j];
#pragma unroll
        for (int cc = 0; cc < 4; cc++) {
            float wv = ws[(chg*4 + cc)*65 + c];
#pragma unroll
            for (int j = 0; j < 16; j++) acc[cc][j] = fmaf(wv, xv[j], acc[cc][j]);
        }
    }
#pragma unroll
    for (int cc = 0; cc < 4; cc++) {
        int ch = chg*4 + cc;
        float s1 = 0.f, s2 = 0.f;
        float* o = out + (size_t)ch*RTOT + r0 + colg;
#pragma unroll
        for (int j = 0; j < 16; j++) {
            float v = acc[cc][j]; o[16*j] = v; s1 += v; s2 = fmaf(v, v, s2);
        }
        sr1[ch*16 + colg] = s1; sr2[ch*16 + colg] = s2;
    }
    __syncthreads();
    for (int ch = t; ch < COUT; ch += NT) {
        float a = 0.f, b2 = 0.f;
#pragma unroll
        for (int k = 0; k < 16; k++) { a += sr1[ch*16 + k]; b2 += sr2[ch*16 + k]; }
        part[((size_t)blockIdx.x*COUT + ch)*2]     = a;
        part[((size_t)blockIdx.x*COUT + ch)*2 + 1] = b2;
    }
}

// ---------------- Last conv: 64 -> 128, fused raw max over each 32-group ----
__global__ __launch_bounds__(512, 1)
void conv_last_kernel(const float* __restrict__ in,
                      const float* __restrict__ A, const float* __restrict__ C,
                      const float* __restrict__ W, const float* __restrict__ B,
                      float* __restrict__ gmax,
                      float* __restrict__ part)
{
    extern __shared__ float sm[];
    float* ins = sm;                 // [64][256]
    float* ws  = sm + 64*256;        // [128][65]
    float* sr1 = ws + 128*65;        // [128][16]
    float* sr2 = sr1 + 128*16;
    const int NT = 512;
    int t = threadIdx.x; size_t r0 = (size_t)blockIdx.x * 256;

    for (int i = t; i < 128*64; i += NT) { int o = i >> 6, c = i & 63; ws[o*65 + c] = W[i]; }
    for (int i = t; i < 64*256; i += NT) {
        int c = i >> 8, col = i & 255;
        float v = fmaf(in[(size_t)c*RTOT + r0 + col], A[c], C[c]);
        ins[i] = fmaxf(v, 0.f);
    }
    __syncthreads();

    int colg = t & 15, chg = t >> 4;
    float acc[4][16];
#pragma unroll
    for (int cc = 0; cc < 4; cc++) {
        float bz = B[chg*4 + cc];
#pragma unroll
        for (int j = 0; j < 16; j++) acc[cc][j] = bz;
    }
    for (int c = 0; c < 64; c++) {
        const float4* xv4 = reinterpret_cast<const float4*>(ins + c*256 + colg*16);
        float4 v0 = xv4[0], v1 = xv4[1], v2 = xv4[2], v3 = xv4[3];
        float xv[16] = {v0.x,v0.y,v0.z,v0.w, v1.x,v1.y,v1.z,v1.w,
                        v2.x,v2.y,v2.z,v2.w, v3.x,v3.y,v3.z,v3.w};
#pragma unroll
        for (int cc = 0; cc < 4; cc++) {
            float wv = ws[(chg*4 + cc)*65 + c];
#pragma unroll
            for (int j = 0; j < 16; j++) acc[cc][j] = fmaf(wv, xv[j], acc[cc][j]);
        }
    }
#pragma unroll
    for (int cc = 0; cc < 4; cc++) {
        int ch = chg*4 + cc;
        float s1 = 0.f, s2 = 0.f;
        float m = acc[cc][0];
#pragma unroll
        for (int j = 0; j < 16; j++) {
            float v = acc[cc][j];
            s1 += v; s2 = fmaf(v, v, s2);
            m = fmaxf(m, v);
        }
        sr1[ch*16 + colg] = s1; sr2[ch*16 + colg] = s2;
        float om = __shfl_xor_sync(0xffffffffu, m, 1);
        m = fmaxf(m, om);
        if ((colg & 1) == 0) {
            size_t grp = (size_t)blockIdx.x*8 + (colg >> 1);
            gmax[grp*128 + ch] = m;
        }
    }
    __syncthreads();
    for (int ch = t; ch < 128; ch += NT) {
        float a = 0.f, b2 = 0.f;
#pragma unroll
        for (int k = 0; k < 16; k++) { a += sr1[ch*16 + k]; b2 += sr2[ch*16 + k]; }
        part[((size_t)blockIdx.x*128 + ch)*2]     = a;
        part[((size_t)blockIdx.x*128 + ch)*2 + 1] = b2;
    }
}

// ---------------- Finalize: out = relu(a * rawmax + c) ----------------------
__global__ __launch_bounds__(256) void finalize_kernel(const float* __restrict__ gmax,
                                                       const float* __restrict__ A,
                                                       const float* __restrict__ C,
                                                       float* __restrict__ dout)
{
    int i = blockIdx.x * 256 + threadIdx.x;
    int ch = i & 127;
    dout[(size_t)BATCH*NPOINT*3 + i] = fmaxf(fmaf(gmax[i], A[ch], C[ch]), 0.f);
}

// ---------------- launch ----------------------------------------------------
extern "C" void kernel_launch(void* const* d_in, const int* in_sizes, int n_in,
                              void* d_out, int out_size)
{
    (void)in_sizes; (void)n_in; (void)out_size;
    const float* xyz = (const float*)d_in[0];
    const float* pts = (const float*)d_in[1];
    const float* w0  = (const float*)d_in[2];  const float* b0  = (const float*)d_in[3];
    const float* g0  = (const float*)d_in[4];  const float* be0 = (const float*)d_in[5];
    const float* w1  = (const float*)d_in[6];  const float* b1  = (const float*)d_in[7];
    const float* g1  = (const float*)d_in[8];  const float* be1 = (const float*)d_in[9];
    const float* w2  = (const float*)d_in[10]; const float* b2  = (const float*)d_in[11];
    const float* g2  = (const float*)d_in[12]; const float* be2 = (const float*)d_in[13];
    float* out = (float*)d_out;

    float *x0, *y0, *y1, *gmax, *part, *A0, *C0, *A1, *C1, *A2, *C2;
    cudaGetSymbolAddress((void**)&x0,   g_x0);
    cudaGetSymbolAddress((void**)&y0,   g_y0);
    cudaGetSymbolAddress((void**)&y1,   g_y1);
    cudaGetSymbolAddress((void**)&gmax, g_gmax);
    cudaGetSymbolAddress((void**)&part, g_part);
    cudaGetSymbolAddress((void**)&A0,   g_A0);  cudaGetSymbolAddress((void**)&C0, g_C0);
    cudaGetSymbolAddress((void**)&A1,   g_A1);  cudaGetSymbolAddress((void**)&C1, g_C1);
    cudaGetSymbolAddress((void**)&A2,   g_A2);  cudaGetSymbolAddress((void**)&C2, g_C2);

    const int C1_SMEM  = (64*256 + 64*65  + 64*16*2)  * 4;       // 90368
    const int C2_SMEM  = (64*256 + 128*65 + 128*16*2) * 4;       // 115200
    cudaFuncSetAttribute(conv_mid_kernel<64>, cudaFuncAttributeMaxDynamicSharedMemorySize, C1_SMEM);
    cudaFuncSetAttribute(conv_last_kernel,    cudaFuncAttributeMaxDynamicSharedMemorySize, C2_SMEM);

    // 5 no-ops shift ncu's "-s 5 -c 1" capture window onto fps_cluster_kernel
    noop_kernel<<<1, 32>>>();
    noop_kernel<<<1, 32>>>();
    noop_kernel<<<1, 32>>>();
    noop_kernel<<<1, 32>>>();
    noop_kernel<<<1, 32>>>();

    fps_cluster_kernel<<<BATCH*FPB, FTH>>>(xyz, out);
    bq_kernel<<<BATCH*NPOINT/8, 256>>>(xyz, pts, out, x0);
    conv0_kernel<<<RTOT/256, 256>>>(x0, w0, b0, y0, part);
    stats_kernel<<<64, 256>>>(part, RTOT/256, 64, g0, be0, A0, C0);
    conv_mid_kernel<64><<<RTOT/256, 256, C1_SMEM>>>(y0, A0, C0, w1, b1, y1, part);
    stats_kernel<<<64, 256>>>(part, RTOT/256, 64, g1, be1, A1, C1);
    conv_last_kernel<<<RTOT/256, 512, C2_SMEM>>>(y1, A1, C1, w2, b2, gmax, part);
    stats_kernel<<<128, 256>>>(part, RTOT/256, 128, g2, be2, A2, C2);
    finalize_kernel<<<BATCH*NPOINT*128/256, 256>>>(gmax, A2, C2, out);
}

// round 15
// speedup vs baseline: 1.6901x; 1.0418x over previous
#include <cuda_runtime.h>
#include <math.h>
#include <stdint.h>

// Problem constants
#define BATCH   8
#define NPTS    16384
#define NPOINT  1024
#define NSAMP   32
#define RTOT    (BATCH*NPOINT*NSAMP)   /* 262144 rows */
#define FPB     8                      /* FPS CTAs per batch (cluster size) */
#define PPC     (NPTS/FPB)             /* 2048 points per CTA */
#define FTH     128                    /* FPS threads per CTA */
#define PPT     (PPC/FTH)              /* 16 points per thread */

// ---------------- scratch (device globals; no allocations allowed) ----------
__device__ float g_x0[(size_t)RTOT*9];        // grouped input, CHANNEL-major [9][RTOT]
__device__ float g_y0[(size_t)64*RTOT];       // layer0 raw out [64][R] (67MB)
__device__ float g_y1[(size_t)64*RTOT];       // layer1 raw out (67MB)
__device__ float g_gmax[(size_t)BATCH*NPOINT*128]; // per-group raw max (4MB)
__device__ float g_part[(size_t)1024*128*2];  // per-block BN partial sums
__device__ float g_A0[64], g_C0[64];
__device__ float g_A1[64], g_C1[64];
__device__ float g_A2[128], g_C2[128];

__device__ __forceinline__ uint32_t s2u(const void* p) {
    return (uint32_t)__cvta_generic_to_shared(p);
}

__device__ __forceinline__ uint32_t mapa_rank(uint32_t a, uint32_t r) {
    uint32_t ra;
    asm volatile("mapa.shared::cluster.u32 %0, %1, %2;" : "=r"(ra) : "r"(a), "r"(r));
    return ra;
}

__device__ __forceinline__ void mbar_wait_cluster(uint32_t a, uint32_t par) {
    uint32_t done = 0;
    do {
        asm volatile(
            "{\n\t.reg .pred p;\n\t"
            "mbarrier.try_wait.parity.acquire.cluster.shared::cta.b64 p, [%1], %2, 0x989680;\n\t"
            "selp.b32 %0, 1, 0, p;\n\t}"
            : "=r"(done) : "r"(a), "r"(par) : "memory");
    } while (!done);
}

__device__ __forceinline__ void mbar_arrive_cluster(uint32_t a) {
    asm volatile("mbarrier.arrive.release.cluster.shared::cluster.b64 _, [%0];"
                 :: "r"(a) : "memory");
}

// ---------------- dummy: shifts ncu's capture window onto fps ---------------
// (2 harness fill launches precede ours; 3 noops put fps at capture index 5)
__global__ void noop_kernel() {}

// ---------------- FPS: 8-CTA cluster, 128 thr x 16 reg-resident points ------
// Identical math/tie-break semantics to the passing version; only the
// thread-count/points-per-thread split changed (li = t + k*FTH still covers
// 0..2047, ascending in k, so strict > keeps the lowest local index).
__global__ __launch_bounds__(FTH,1) __cluster_dims__(FPB,1,1)
void fps_cluster_kernel(const float* __restrict__ xyz, float* __restrict__ dout)
{
    __shared__ float sxl[PPC], syl[PPC], szl[PPC];
    __shared__ unsigned redK[4]; __shared__ int redI[4];
    __shared__ __align__(16) float gbuf[2][FPB][4];   // [parity][src rank][{k,x,y,z}]
    __shared__ __align__(8) unsigned long long mb_bcast;

    int t = threadIdx.x;
    unsigned rank; asm("mov.u32 %0, %%cluster_ctarank;" : "=r"(rank));
    int b = blockIdx.x / FPB;
    const float* X = xyz + (size_t)b*NPTS*3;
    int base = (int)rank * PPC;

    float px[PPT], py[PPT], pz[PPT], pd[PPT];
#pragma unroll
    for (int k = 0; k < PPT; k++) {
        int li = t + k*FTH;               // local index, ascending in k
        int gp = base + li;
        px[k] = X[3*gp]; py[k] = X[3*gp+1]; pz[k] = X[3*gp+2];
        sxl[li] = px[k]; syl[li] = py[k]; szl[li] = pz[k];
        pd[k] = 1e10f;
    }
    float cx = X[0], cy = X[1], cz = X[2];   // deterministic start at index 0

    if (t == 0) {
        uint32_t mbc = s2u(&mb_bcast);
        asm volatile("mbarrier.init.shared.b64 [%0], %1;" :: "r"(mbc), "r"((uint32_t)FPB) : "memory");
    }
    __syncthreads();
    asm volatile("barrier.cluster.arrive.aligned;" ::: "memory");
    asm volatile("barrier.cluster.wait.aligned;"   ::: "memory");

    int lane = t & 31, w = t >> 5;        // 4 warps
    uint32_t pdst0 = 0, pdst1 = 0, pmb = 0;
    if (w == 0 && lane < FPB) {
        pdst0 = mapa_rank(s2u(&gbuf[0][rank][0]), (uint32_t)lane);
        pdst1 = mapa_rank(s2u(&gbuf[1][rank][0]), (uint32_t)lane);
        pmb   = mapa_rank(s2u(&mb_bcast),         (uint32_t)lane);
    }
    uint32_t my_bcast = s2u(&mb_bcast);
    float* co = dout + (size_t)b*NPOINT*3;

    for (int it = 0; it < NPOINT; it++) {
        if (rank == 0 && t == 0) { co[3*it] = cx; co[3*it+1] = cy; co[3*it+2] = cz; }

        // exact XLA lowering per point: sub, mul, add-add (no FMA contraction)
        float best = -1.0f; int bi = 0;
#pragma unroll
        for (int k = 0; k < PPT; k++) {
            float dx = __fsub_rn(px[k], cx);
            float dy = __fsub_rn(py[k], cy);
            float dz = __fsub_rn(pz[k], cz);
            float d  = __fadd_rn(__fadd_rn(__fmul_rn(dx,dx), __fmul_rn(dy,dy)),
                                 __fmul_rn(dz,dz));
            float nd = fminf(pd[k], d);
            pd[k] = nd;
            if (nd > best) { best = nd; bi = t + k*FTH; }  // strict >: lowest li
        }

        unsigned kk = __float_as_uint(best);
        unsigned wm = __reduce_max_sync(0xffffffffu, kk);
        unsigned wbi = __reduce_min_sync(0xffffffffu,
                                         (kk == wm) ? (unsigned)bi : 0xffffffffu);
        if (lane == 0) { redK[w] = wm; redI[w] = (int)wbi; }
        __syncthreads();

        int par = it & 1;
        if (w == 0) {
            unsigned k2 = (lane < 4) ? redK[lane] : 0u;
            unsigned i2 = (lane < 4) ? (unsigned)redI[lane] : 0xffffffffu;
            unsigned m2 = __reduce_max_sync(0xffffffffu, k2);
            unsigned wi = __reduce_min_sync(0xffffffffu,
                                            (k2 == m2) ? i2 : 0xffffffffu);
            if (lane < FPB) {
                int loc = (int)wi;                   // uniform -> broadcast LDS
                float lx = sxl[loc], ly = syl[loc], lz = szl[loc];
                uint32_t dst = par ? pdst1 : pdst0;  // lane's peer CTA slot
                asm volatile("st.shared::cluster.b32 [%0],    %1;" :: "r"(dst), "r"(m2) : "memory");
                asm volatile("st.shared::cluster.b32 [%0+4],  %1;" :: "r"(dst), "f"(lx) : "memory");
                asm volatile("st.shared::cluster.b32 [%0+8],  %1;" :: "r"(dst), "f"(ly) : "memory");
                asm volatile("st.shared::cluster.b32 [%0+12], %1;" :: "r"(dst), "f"(lz) : "memory");
                mbar_arrive_cluster(pmb);
            }
        }
        mbar_wait_cluster(my_bcast, (uint32_t)par);

        // scan 8 records ascending rank; strict > keeps lowest rank on ties
        unsigned bk = __float_as_uint(gbuf[par][0][0]);
        int br = 0;
#pragma unroll
        for (int r = 1; r < FPB; r++) {
            unsigned kr = __float_as_uint(gbuf[par][r][0]);
            if (kr > bk) { bk = kr; br = r; }
        }
        cx = gbuf[par][br][1]; cy = gbuf[par][br][2]; cz = gbuf[par][br][3];
    }
    asm volatile("barrier.cluster.arrive.aligned;" ::: "memory");
    asm volatile("barrier.cluster.wait.aligned;"   ::: "memory");
}

// ---------------- Ball query + gather + concat: one warp per centroid -------
// Output x0 is CHANNEL-major [9][RTOT]; per-warp stores stay fully coalesced.
__global__ __launch_bounds__(256) void bq_kernel(const float* __restrict__ xyz,
                                                 const float* __restrict__ pts,
                                                 const float* __restrict__ cent,
                                                 float* __restrict__ x0)
{
    __shared__ int sbuf[8][NSAMP];
    int w = threadIdx.x >> 5, lane = threadIdx.x & 31;
    int wg = blockIdx.x * 8 + w;
    int b  = wg >> 10;
    const float* X = xyz + (size_t)b*NPTS*3;

    float cx = cent[3*wg], cy = cent[3*wg+1], cz = cent[3*wg+2];
    const float R2 = (float)(0.2*0.2);    // f32(0.04), NOT 0.2f*0.2f
    float sc = __fadd_rn(__fadd_rn(__fmul_rn(cx,cx), __fmul_rn(cy,cy)),
                         __fmul_rn(cz,cz));
    sbuf[w][lane] = 0;
    __syncwarp();

    int count = 0;
    for (int base = 0; base < NPTS; base += 32) {
        int p = base + lane;
        float x = X[3*p], y = X[3*p+1], z = X[3*p+2];
        float dot = __fadd_rn(__fadd_rn(__fmul_rn(cx,x), __fmul_rn(cy,y)),
                              __fmul_rn(cz,z));
        float sx2 = __fadd_rn(__fadd_rn(__fmul_rn(x,x), __fmul_rn(y,y)),
                              __fmul_rn(z,z));
        float d2  = __fadd_rn(__fsub_rn(sc, __fmul_rn(2.0f, dot)), sx2);
        bool in = d2 < R2;
        unsigned m = __ballot_sync(0xffffffffu, in);
        if (in) {
            int pos = count + __popc(m & ((1u << lane) - 1u));
            if (pos < NSAMP) sbuf[w][pos] = p;
        }
        count += __popc(m);
        if (count >= NSAMP) break;        // warp-uniform
    }
    __syncwarp();

    int idx = sbuf[w][lane];
    const float* PT = pts + (size_t)b*NPTS*6;
    size_t row = (size_t)wg*NSAMP + lane;
    x0[0*(size_t)RTOT + row] = __fsub_rn(X[3*idx],   cx);
    x0[1*(size_t)RTOT + row] = __fsub_rn(X[3*idx+1], cy);
    x0[2*(size_t)RTOT + row] = __fsub_rn(X[3*idx+2], cz);
#pragma unroll
    for (int k = 0; k < 6; k++) x0[(3+k)*(size_t)RTOT + row] = PT[6*idx+k];
}

// ---------------- Layer 0: 9 -> 64, channel-major in/out, float4 GEMM -------
__global__ __launch_bounds__(256) void conv0_kernel(const float* __restrict__ x0,
                                                    const float* __restrict__ W,
                                                    const float* __restrict__ B,
                                                    float* __restrict__ y,
                                                    float* __restrict__ part)
{
    __shared__ float ins[9*256];
    __shared__ float sr1[64*16], sr2[64*16];
    int t = threadIdx.x; size_t r0 = (size_t)blockIdx.x * 256;

    for (int i = t; i < 9*64; i += 256) {           // 9*256 floats as float4
        int c = i / 64, col4 = i % 64;
        float4 v = *reinterpret_cast<const float4*>(x0 + (size_t)c*RTOT + r0 + col4*4);
        *reinterpret_cast<float4*>(ins + c*256 + col4*4) = v;
    }
    int colg = t & 15, chg = t >> 4;                // 16 cols x 4 out-ch
    float wv[4][9];
#pragma unroll
    for (int cc = 0; cc < 4; cc++)
#pragma unroll
        for (int c = 0; c < 9; c++) wv[cc][c] = W[(chg*4+cc)*9 + c];
    __syncthreads();

    float acc[4][16];
#pragma unroll
    for (int cc = 0; cc < 4; cc++) {
        float bz = B[chg*4 + cc];
#pragma unroll
        for (int j = 0; j < 16; j++) acc[cc][j] = bz;
    }
#pragma unroll
    for (int c = 0; c < 9; c++) {
        const float4* xv4 = reinterpret_cast<const float4*>(ins + c*256 + colg*16);
        float4 v0 = xv4[0], v1 = xv4[1], v2 = xv4[2], v3 = xv4[3];
        float xv[16] = {v0.x,v0.y,v0.z,v0.w, v1.x,v1.y,v1.z,v1.w,
                        v2.x,v2.y,v2.z,v2.w, v3.x,v3.y,v3.z,v3.w};
#pragma unroll
        for (int cc = 0; cc < 4; cc++)
#pragma unroll
            for (int j = 0; j < 16; j++) acc[cc][j] = fmaf(wv[cc][c], xv[j], acc[cc][j]);
    }
#pragma unroll
    for (int cc = 0; cc < 4; cc++) {
        int ch = chg*4 + cc;
        float s1 = 0.f, s2 = 0.f;
        float* o = y + (size_t)ch*RTOT + r0 + colg*16;
#pragma unroll
        for (int j = 0; j < 4; j++) {
            float4 v = make_float4(acc[cc][4*j], acc[cc][4*j+1], acc[cc][4*j+2], acc[cc][4*j+3]);
            *reinterpret_cast<float4*>(o + 4*j) = v;
        }
#pragma unroll
        for (int j = 0; j < 16; j++) { float v = acc[cc][j]; s1 += v; s2 = fmaf(v, v, s2); }
        sr1[ch*16 + colg] = s1; sr2[ch*16 + colg] = s2;
    }
    __syncthreads();
    for (int ch = t; ch < 64; ch += 256) {
        float a = 0.f, b2 = 0.f;
#pragma unroll
        for (int k = 0; k < 16; k++) { a += sr1[ch*16 + k]; b2 += sr2[ch*16 + k]; }
        part[((size_t)blockIdx.x*64 + ch)*2]     = a;
        part[((size_t)blockIdx.x*64 + ch)*2 + 1] = b2;
    }
}

// ---------------- BN stat finalize (deterministic, double accumulation) -----
__global__ __launch_bounds__(256) void stats_kernel(const float* __restrict__ part,
                                                    int nblk, int cout,
                                                    const float* __restrict__ g,
                                                    const float* __restrict__ be,
                                                    float* __restrict__ A,
                                                    float* __restrict__ C)
{
    __shared__ double r1[256], r2[256];
    int ch = blockIdx.x, t = threadIdx.x;
    double s1 = 0.0, s2 = 0.0;
    for (int i = t; i < nblk; i += 256) {
        const float* p = part + ((size_t)i*cout + ch)*2;
        s1 += (double)p[0]; s2 += (double)p[1];
    }
    r1[t] = s1; r2[t] = s2; __syncthreads();
    for (int o = 128; o > 0; o >>= 1) {
        if (t < o) { r1[t] += r1[t+o]; r2[t] += r2[t+o]; }
        __syncthreads();
    }
    if (t == 0) {
        double n = (double)RTOT;
        double mean = r1[0] / n;
        double var  = r2[0] / n - mean*mean;
        float rstd = (float)(1.0 / sqrt(var + 1e-5));
        float a = g[ch] * rstd;
        float c = be[ch] - (float)mean * a;
        A[ch] = a; C[ch] = c;
    }
}

// ---------------- Mid conv: 64 -> 64, float4 everywhere ----------------------
template<int COUT>
__global__ __launch_bounds__(COUT*4, 1)
void conv_mid_kernel(const float* __restrict__ in,
                     const float* __restrict__ A, const float* __restrict__ C,
                     const float* __restrict__ W, const float* __restrict__ B,
                     float* __restrict__ out,
                     float* __restrict__ part)
{
    extern __shared__ float sm[];
    float* ins = sm;                 // [64][256]
    float* ws  = sm + 64*256;        // [COUT][65] padded
    float* sr1 = ws + COUT*65;       // [COUT][16]
    float* sr2 = sr1 + COUT*16;
    const int NT = COUT*4;
    int t = threadIdx.x; size_t r0 = (size_t)blockIdx.x * 256;

    for (int i = t; i < COUT*64; i += NT) { int o = i >> 6, c = i & 63; ws[o*65 + c] = W[i]; }
    for (int i = t; i < 64*64; i += NT) {            // 64*256 floats as float4
        int c = i >> 6, col4 = i & 63;
        float4 v = *reinterpret_cast<const float4*>(in + (size_t)c*RTOT + r0 + col4*4);
        float a = A[c], cc0 = C[c];
        v.x = fmaxf(fmaf(v.x, a, cc0), 0.f);
        v.y = fmaxf(fmaf(v.y, a, cc0), 0.f);
        v.z = fmaxf(fmaf(v.z, a, cc0), 0.f);
        v.w = fmaxf(fmaf(v.w, a, cc0), 0.f);
        *reinterpret_cast<float4*>(ins + c*256 + col4*4) = v;
    }
    __syncthreads();

    int colg = t & 15, chg = t >> 4;       // contiguous 16 cols per thread
    float acc[4][16];
#pragma unroll
    for (int cc = 0; cc < 4; cc++) {
        float bz = B[chg*4 + cc];
#pragma unroll
        for (int j = 0; j < 16; j++) acc[cc][j] = bz;
    }
    for (int c = 0; c < 64; c++) {
        const float4* xv4 = reinterpret_cast<const float4*>(ins + c*256 + colg*16);
        float4 v0 = xv4[0], v1 = xv4[1], v2 = xv4[2], v3 = xv4[3];
        float xv[16] = {v0.x,v0.y,v0.z,v0.w, v1.x,v1.y,v1.z,v1.w,
                        v2.x,v2.y,v2.z,v2.w, v3.x,v3.y,v3.z,v3.w};
#pragma unroll
        for (int cc = 0; cc < 4; cc++) {
            float wv = ws[(chg*4 + cc)*65 + c];
#pragma unroll
            for (int j = 0; j < 16; j++) acc[cc][j] = fmaf(wv, xv[j], acc[cc][j]);
        }
    }
#pragma unroll
    for (int cc = 0; cc < 4; cc++) {
        int ch = chg*4 + cc;
        float s1 = 0.f, s2 = 0.f;
        float* o = out + (size_t)ch*RTOT + r0 + colg*16;
#pragma unroll
        for (int j = 0; j < 4; j++) {
            float4 v = make_float4(acc[cc][4*j], acc[cc][4*j+1], acc[cc][4*j+2], acc[cc][4*j+3]);
            *reinterpret_cast<float4*>(o + 4*j) = v;
        }
#pragma unroll
        for (int j = 0; j < 16; j++) { float v = acc[cc][j]; s1 += v; s2 = fmaf(v, v, s2); }
        sr1[ch*16 + colg] = s1; sr2[ch*16 + colg] = s2;
    }
    __syncthreads();
    for (int ch = t; ch < COUT; ch += NT) {
        float a = 0.f, b2 = 0.f;
#pragma unroll
        for (int k = 0; k < 16; k++) { a += sr1[ch*16 + k]; b2 += sr2[ch*16 + k]; }
        part[((size_t)blockIdx.x*COUT + ch)*2]     = a;
        part[((size_t)blockIdx.x*COUT + ch)*2 + 1] = b2;
    }
}

// ---------------- Last conv: 64 -> 128, fused raw max over each 32-group ----
__global__ __launch_bounds__(512, 1)
void conv_last_kernel(const float* __restrict__ in,
                      const float* __restrict__ A, const float* __restrict__ C,
                      const float* __restrict__ W, const float* __restrict__ B,
                      float* __restrict__ gmax,
                      float* __restrict__ part)
{
    extern __shared__ float sm[];
    float* ins = sm;                 // [64][256]
    float* ws  = sm + 64*256;        // [128][65]
    float* sr1 = ws + 128*65;        // [128][16]
    float* sr2 = sr1 + 128*16;
    const int NT = 512;
    int t = threadIdx.x; size_t r0 = (size_t)blockIdx.x * 256;

    for (int i = t; i < 128*64; i += NT) { int o = i >> 6, c = i & 63; ws[o*65 + c] = W[i]; }
    for (int i = t; i < 64*64; i += NT) {            // float4 load path
        int c = i >> 6, col4 = i & 63;
        float4 v = *reinterpret_cast<const float4*>(in + (size_t)c*RTOT + r0 + col4*4);
        float a = A[c], cc0 = C[c];
        v.x = fmaxf(fmaf(v.x, a, cc0), 0.f);
        v.y = fmaxf(fmaf(v.y, a, cc0), 0.f);
        v.z = fmaxf(fmaf(v.z, a, cc0), 0.f);
        v.w = fmaxf(fmaf(v.w, a, cc0), 0.f);
        *reinterpret_cast<float4*>(ins + c*256 + col4*4) = v;
    }
    __syncthreads();

    int colg = t & 15, chg = t >> 4;
    float acc[4][16];
#pragma unroll
    for (int cc = 0; cc < 4; cc++) {
        float bz = B[chg*4 + cc];
#pragma unroll
        for (int j = 0; j < 16; j++) acc[cc][j] = bz;
    }
    for (int c = 0; c < 64; c++) {
        const float4* xv4 = reinterpret_cast<const float4*>(ins + c*256 + colg*16);
        float4 v0 = xv4[0], v1 = xv4[1], v2 = xv4[2], v3 = xv4[3];
        float xv[16] = {v0.x,v0.y,v0.z,v0.w, v1.x,v1.y,v1.z,v1.w,
                        v2.x,v2.y,v2.z,v2.w, v3.x,v3.y,v3.z,v3.w};
#pragma unroll
        for (int cc = 0; cc < 4; cc++) {
            float wv = ws[(chg*4 + cc)*65 + c];
#pragma unroll
            for (int j = 0; j < 16; j++) acc[cc][j] = fmaf(wv, xv[j], acc[cc][j]);
        }
    }
#pragma unroll
    for (int cc = 0; cc < 4; cc++) {
        int ch = chg*4 + cc;
        float s1 = 0.f, s2 = 0.f;
        float m = acc[cc][0];
#pragma unroll
        for (int j = 0; j < 16; j++) {
            float v = acc[cc][j];
            s1 += v; s2 = fmaf(v, v, s2);
            m = fmaxf(m, v);
        }
        sr1[ch*16 + colg] = s1; sr2[ch*16 + colg] = s2;
        float om = __shfl_xor_sync(0xffffffffu, m, 1);   // partner half of 32-group
        m = fmaxf(m, om);
        if ((colg & 1) == 0) {
            size_t grp = (size_t)blockIdx.x*8 + (colg >> 1);
            gmax[grp*128 + ch] = m;
        }
    }
    __syncthreads();
    for (int ch = t; ch < 128; ch += NT) {
        float a = 0.f, b2 = 0.f;
#pragma unroll
        for (int k = 0; k < 16; k++) { a += sr1[ch*16 + k]; b2 += sr2[ch*16 + k]; }
        part[((size_t)blockIdx.x*128 + ch)*2]     = a;
        part[((size_t)blockIdx.x*128 + ch)*2 + 1] = b2;
    }
}

// ---------------- Finalize: out = relu(a * rawmax + c) ----------------------
__global__ __launch_bounds__(256) void finalize_kernel(const float* __restrict__ gmax,
                                                       const float* __restrict__ A,
                                                       const float* __restrict__ C,
                                                       float* __restrict__ dout)
{
    int i = blockIdx.x * 256 + threadIdx.x;
    int ch = i & 127;
    dout[(size_t)BATCH*NPOINT*3 + i] = fmaxf(fmaf(gmax[i], A[ch], C[ch]), 0.f);
}

// ---------------- launch ----------------------------------------------------
extern "C" void kernel_launch(void* const* d_in, const int* in_sizes, int n_in,
                              void* d_out, int out_size)
{
    (void)in_sizes; (void)n_in; (void)out_size;
    const float* xyz = (const float*)d_in[0];
    const float* pts = (const float*)d_in[1];
    const float* w0  = (const float*)d_in[2];  const float* b0  = (const float*)d_in[3];
    const float* g0  = (const float*)d_in[4];  const float* be0 = (const float*)d_in[5];
    const float* w1  = (const float*)d_in[6];  const float* b1  = (const float*)d_in[7];
    const float* g1  = (const float*)d_in[8];  const float* be1 = (const float*)d_in[9];
    const float* w2  = (const float*)d_in[10]; const float* b2  = (const float*)d_in[11];
    const float* g2  = (const float*)d_in[12]; const float* be2 = (const float*)d_in[13];
    float* out = (float*)d_out;

    float *x0, *y0, *y1, *gmax, *part, *A0, *C0, *A1, *C1, *A2, *C2;
    cudaGetSymbolAddress((void**)&x0,   g_x0);
    cudaGetSymbolAddress((void**)&y0,   g_y0);
    cudaGetSymbolAddress((void**)&y1,   g_y1);
    cudaGetSymbolAddress((void**)&gmax, g_gmax);
    cudaGetSymbolAddress((void**)&part, g_part);
    cudaGetSymbolAddress((void**)&A0,   g_A0);  cudaGetSymbolAddress((void**)&C0, g_C0);
    cudaGetSymbolAddress((void**)&A1,   g_A1);  cudaGetSymbolAddress((void**)&C1, g_C1);
    cudaGetSymbolAddress((void**)&A2,   g_A2);  cudaGetSymbolAddress((void**)&C2, g_C2);

    const int C1_SMEM  = (64*256 + 64*65  + 64*16*2)  * 4;       // 90368
    const int C2_SMEM  = (64*256 + 128*65 + 128*16*2) * 4;       // 115200
    cudaFuncSetAttribute(conv_mid_kernel<64>, cudaFuncAttributeMaxDynamicSharedMemorySize, C1_SMEM);
    cudaFuncSetAttribute(conv_last_kernel,    cudaFuncAttributeMaxDynamicSharedMemorySize, C2_SMEM);

    // 3 noops: with the 2 harness fill launches, fps lands at ncu capture idx 5
    noop_kernel<<<1, 32>>>();
    noop_kernel<<<1, 32>>>();
    noop_kernel<<<1, 32>>>();

    fps_cluster_kernel<<<BATCH*FPB, FTH>>>(xyz, out);
    bq_kernel<<<BATCH*NPOINT/8, 256>>>(xyz, pts, out, x0);
    conv0_kernel<<<RTOT/256, 256>>>(x0, w0, b0, y0, part);
    stats_kernel<<<64, 256>>>(part, RTOT/256, 64, g0, be0, A0, C0);
    conv_mid_kernel<64><<<RTOT/256, 256, C1_SMEM>>>(y0, A0, C0, w1, b1, y1, part);
    stats_kernel<<<64, 256>>>(part, RTOT/256, 64, g1, be1, A1, C1);
    conv_last_kernel<<<RTOT/256, 512, C2_SMEM>>>(y1, A1, C1, w2, b2, gmax, part);
    stats_kernel<<<128, 256>>>(part, RTOT/256, 128, g2, be2, A2, C2);
    finalize_kernel<<<BATCH*NPOINT*128/256, 256>>>(gmax, A2, C2, out);
}

// round 16
// speedup vs baseline: 2.0302x; 1.2012x over previous
#include <cuda_runtime.h>
#include <math.h>
#include <stdint.h>

// Problem constants
#define BATCH   8
#define NPTS    16384
#define NPOINT  1024
#define NSAMP   32
#define RTOT    (BATCH*NPOINT*NSAMP)   /* 262144 rows */
#define FPB     8                      /* FPS CTAs per batch (cluster size) */
#define PPC     (NPTS/FPB)             /* 2048 points per CTA */
#define FTH     128                    /* FPS threads per CTA */
#define PPT     (PPC/FTH)              /* 16 points per thread */

// ---------------- scratch (device globals; no allocations allowed) ----------
__device__ float g_y0[(size_t)64*RTOT];       // layer0 raw out [64][R] (67MB)
__device__ float g_y1[(size_t)64*RTOT];       // layer1 raw out (67MB)
__device__ float g_gmax[(size_t)BATCH*NPOINT*128]; // per-group raw max (4MB)
__device__ float g_part[(size_t)1024*128*2];  // per-block BN partial sums
__device__ float g_A0[64], g_C0[64];
__device__ float g_A1[64], g_C1[64];
__device__ float g_A2[128], g_C2[128];

__device__ __forceinline__ uint32_t s2u(const void* p) {
    return (uint32_t)__cvta_generic_to_shared(p);
}

__device__ __forceinline__ uint32_t mapa_rank(uint32_t a, uint32_t r) {
    uint32_t ra;
    asm volatile("mapa.shared::cluster.u32 %0, %1, %2;" : "=r"(ra) : "r"(a), "r"(r));
    return ra;
}

__device__ __forceinline__ void mbar_wait_cluster(uint32_t a, uint32_t par) {
    uint32_t done = 0;
    do {
        asm volatile(
            "{\n\t.reg .pred p;\n\t"
            "mbarrier.try_wait.parity.acquire.cluster.shared::cta.b64 p, [%1], %2, 0x989680;\n\t"
            "selp.b32 %0, 1, 0, p;\n\t}"
            : "=r"(done) : "r"(a), "r"(par) : "memory");
    } while (!done);
}

__device__ __forceinline__ void mbar_arrive_cluster(uint32_t a) {
    asm volatile("mbarrier.arrive.release.cluster.shared::cluster.b64 _, [%0];"
                 :: "r"(a) : "memory");
}

// 16B-unit xor swizzle: permutes units within aligned 8-unit (128B) blocks.
// Readers (unit = 4*colg+j) land 2 lanes/bank-group (optimal); writers
// (consecutive units) stay conflict-free.
__device__ __forceinline__ int swz(int u) { return u ^ ((u >> 3) & 7); }

// ---------------- FPS: 8-CTA cluster, 128 thr x 16 reg-resident points ------
// (unchanged from the passing R15 kernel; bit-exact vs XLA)
__global__ __launch_bounds__(FTH,1) __cluster_dims__(FPB,1,1)
void fps_cluster_kernel(const float* __restrict__ xyz, float* __restrict__ dout)
{
    __shared__ float sxl[PPC], syl[PPC], szl[PPC];
    __shared__ unsigned redK[4]; __shared__ int redI[4];
    __shared__ __align__(16) float gbuf[2][FPB][4];   // [parity][src rank][{k,x,y,z}]
    __shared__ __align__(8) unsigned long long mb_bcast;

    int t = threadIdx.x;
    unsigned rank; asm("mov.u32 %0, %%cluster_ctarank;" : "=r"(rank));
    int b = blockIdx.x / FPB;
    const float* X = xyz + (size_t)b*NPTS*3;
    int base = (int)rank * PPC;

    float px[PPT], py[PPT], pz[PPT], pd[PPT];
#pragma unroll
    for (int k = 0; k < PPT; k++) {
        int li = t + k*FTH;               // local index, ascending in k
        int gp = base + li;
        px[k] = X[3*gp]; py[k] = X[3*gp+1]; pz[k] = X[3*gp+2];
        sxl[li] = px[k]; syl[li] = py[k]; szl[li] = pz[k];
        pd[k] = 1e10f;
    }
    float cx = X[0], cy = X[1], cz = X[2];   // deterministic start at index 0

    if (t == 0) {
        uint32_t mbc = s2u(&mb_bcast);
        asm volatile("mbarrier.init.shared.b64 [%0], %1;" :: "r"(mbc), "r"((uint32_t)FPB) : "memory");
    }
    __syncthreads();
    asm volatile("barrier.cluster.arrive.aligned;" ::: "memory");
    asm volatile("barrier.cluster.wait.aligned;"   ::: "memory");

    int lane = t & 31, w = t >> 5;        // 4 warps
    uint32_t pdst0 = 0, pdst1 = 0, pmb = 0;
    if (w == 0 && lane < FPB) {
        pdst0 = mapa_rank(s2u(&gbuf[0][rank][0]), (uint32_t)lane);
        pdst1 = mapa_rank(s2u(&gbuf[1][rank][0]), (uint32_t)lane);
        pmb   = mapa_rank(s2u(&mb_bcast),         (uint32_t)lane);
    }
    uint32_t my_bcast = s2u(&mb_bcast);
    float* co = dout + (size_t)b*NPOINT*3;

    for (int it = 0; it < NPOINT; it++) {
        if (rank == 0 && t == 0) { co[3*it] = cx; co[3*it+1] = cy; co[3*it+2] = cz; }

        // exact XLA lowering per point: sub, mul, add-add (no FMA contraction)
        float best = -1.0f; int bi = 0;
#pragma unroll
        for (int k = 0; k < PPT; k++) {
            float dx = __fsub_rn(px[k], cx);
            float dy = __fsub_rn(py[k], cy);
            float dz = __fsub_rn(pz[k], cz);
            float d  = __fadd_rn(__fadd_rn(__fmul_rn(dx,dx), __fmul_rn(dy,dy)),
                                 __fmul_rn(dz,dz));
            float nd = fminf(pd[k], d);
            pd[k] = nd;
            if (nd > best) { best = nd; bi = t + k*FTH; }  // strict >: lowest li
        }

        unsigned kk = __float_as_uint(best);
        unsigned wm = __reduce_max_sync(0xffffffffu, kk);
        unsigned wbi = __reduce_min_sync(0xffffffffu,
                                         (kk == wm) ? (unsigned)bi : 0xffffffffu);
        if (lane == 0) { redK[w] = wm; redI[w] = (int)wbi; }
        __syncthreads();

        int par = it & 1;
        if (w == 0) {
            unsigned k2 = (lane < 4) ? redK[lane] : 0u;
            unsigned i2 = (lane < 4) ? (unsigned)redI[lane] : 0xffffffffu;
            unsigned m2 = __reduce_max_sync(0xffffffffu, k2);
            unsigned wi = __reduce_min_sync(0xffffffffu,
                                            (k2 == m2) ? i2 : 0xffffffffu);
            if (lane < FPB) {
                int loc = (int)wi;                   // uniform -> broadcast LDS
                float lx = sxl[loc], ly = syl[loc], lz = szl[loc];
                uint32_t dst = par ? pdst1 : pdst0;  // lane's peer CTA slot
                asm volatile("st.shared::cluster.b32 [%0],    %1;" :: "r"(dst), "r"(m2) : "memory");
                asm volatile("st.shared::cluster.b32 [%0+4],  %1;" :: "r"(dst), "f"(lx) : "memory");
                asm volatile("st.shared::cluster.b32 [%0+8],  %1;" :: "r"(dst), "f"(ly) : "memory");
                asm volatile("st.shared::cluster.b32 [%0+12], %1;" :: "r"(dst), "f"(lz) : "memory");
                mbar_arrive_cluster(pmb);
            }
        }
        mbar_wait_cluster(my_bcast, (uint32_t)par);

        // scan 8 records ascending rank; strict > keeps lowest rank on ties
        unsigned bk = __float_as_uint(gbuf[par][0][0]);
        int br = 0;
#pragma unroll
        for (int r = 1; r < FPB; r++) {
            unsigned kr = __float_as_uint(gbuf[par][r][0]);
            if (kr > bk) { bk = kr; br = r; }
        }
        cx = gbuf[par][br][1]; cy = gbuf[par][br][2]; cz = gbuf[par][br][3];
    }
    asm volatile("barrier.cluster.arrive.aligned;" ::: "memory");
    asm volatile("barrier.cluster.wait.aligned;"   ::: "memory");
}

// ---------------- FUSED: ball query + gather + conv0 (9 -> 64) --------------
// One warp gathers one centroid's 32 rows straight into the swizzled smem
// tile (no gmem x0 roundtrip); 8 warps = one 256-row conv0 tile; then the
// same float4 GEMM as before, with conflict-free swizzled reads.
__global__ __launch_bounds__(256) void bqconv0_kernel(
    const float* __restrict__ xyz, const float* __restrict__ pts,
    const float* __restrict__ cent,
    const float* __restrict__ W, const float* __restrict__ B,
    float* __restrict__ y, float* __restrict__ part)
{
    __shared__ float ins[9*256];     // swizzled [9][256]
    __shared__ float sr1[64*16], sr2[64*16];
    __shared__ int sbuf[8][NSAMP];
    int t = threadIdx.x;
    int w = t >> 5, lane = t & 31;
    int wg = blockIdx.x * 8 + w;
    int b  = wg >> 10;
    const float* X = xyz + (size_t)b*NPTS*3;

    float cx = cent[3*wg], cy = cent[3*wg+1], cz = cent[3*wg+2];
    const float R2 = (float)(0.2*0.2);    // f32(0.04), NOT 0.2f*0.2f
    float sc = __fadd_rn(__fadd_rn(__fmul_rn(cx,cx), __fmul_rn(cy,cy)),
                         __fmul_rn(cz,cz));
    sbuf[w][lane] = 0;
    __syncwarp();

    int count = 0;
    for (int base = 0; base < NPTS; base += 32) {
        int p = base + lane;
        float x = X[3*p], y2 = X[3*p+1], z = X[3*p+2];
        float dot = __fadd_rn(__fadd_rn(__fmul_rn(cx,x), __fmul_rn(cy,y2)),
                              __fmul_rn(cz,z));
        float sx2 = __fadd_rn(__fadd_rn(__fmul_rn(x,x), __fmul_rn(y2,y2)),
                              __fmul_rn(z,z));
        float d2  = __fadd_rn(__fsub_rn(sc, __fmul_rn(2.0f, dot)), sx2);
        bool in = d2 < R2;
        unsigned m = __ballot_sync(0xffffffffu, in);
        if (in) {
            int pos = count + __popc(m & ((1u << lane) - 1u));
            if (pos < NSAMP) sbuf[w][pos] = p;
        }
        count += __popc(m);
        if (count >= NSAMP) break;        // warp-uniform
    }
    __syncwarp();

    int idx = sbuf[w][lane];
    const float* PT = pts + (size_t)b*NPTS*6;
    int col = w*32 + lane;
    float* base9 = ins + swz(col >> 2)*4 + (col & 3);
    base9[0*256] = __fsub_rn(X[3*idx],   cx);
    base9[1*256] = __fsub_rn(X[3*idx+1], cy);
    base9[2*256] = __fsub_rn(X[3*idx+2], cz);
#pragma unroll
    for (int k = 0; k < 6; k++) base9[(3+k)*256] = PT[6*idx+k];

    int colg = t & 15, chg = t >> 4;
    float wv[4][9];
#pragma unroll
    for (int cc = 0; cc < 4; cc++)
#pragma unroll
        for (int c = 0; c < 9; c++) wv[cc][c] = W[(chg*4+cc)*9 + c];
    __syncthreads();

    float acc[4][16];
#pragma unroll
    for (int cc = 0; cc < 4; cc++) {
        float bz = B[chg*4 + cc];
#pragma unroll
        for (int j = 0; j < 16; j++) acc[cc][j] = bz;
    }
#pragma unroll
    for (int c = 0; c < 9; c++) {
        float xv[16];
#pragma unroll
        for (int j = 0; j < 4; j++) {
            float4 v = *reinterpret_cast<const float4*>(ins + c*256 + swz(colg*4+j)*4);
            xv[4*j] = v.x; xv[4*j+1] = v.y; xv[4*j+2] = v.z; xv[4*j+3] = v.w;
        }
#pragma unroll
        for (int cc = 0; cc < 4; cc++)
#pragma unroll
            for (int j = 0; j < 16; j++) acc[cc][j] = fmaf(wv[cc][c], xv[j], acc[cc][j]);
    }
    size_t r0 = (size_t)blockIdx.x * 256;
#pragma unroll
    for (int cc = 0; cc < 4; cc++) {
        int ch = chg*4 + cc;
        float s1 = 0.f, s2 = 0.f;
        float* o = y + (size_t)ch*RTOT + r0 + colg*16;
#pragma unroll
        for (int j = 0; j < 4; j++) {
            float4 v = make_float4(acc[cc][4*j], acc[cc][4*j+1], acc[cc][4*j+2], acc[cc][4*j+3]);
            *reinterpret_cast<float4*>(o + 4*j) = v;
        }
#pragma unroll
        for (int j = 0; j < 16; j++) { float v = acc[cc][j]; s1 += v; s2 = fmaf(v, v, s2); }
        sr1[ch*16 + colg] = s1; sr2[ch*16 + colg] = s2;
    }
    __syncthreads();
    for (int ch = t; ch < 64; ch += 256) {
        float a = 0.f, b2 = 0.f;
#pragma unroll
        for (int k = 0; k < 16; k++) { a += sr1[ch*16 + k]; b2 += sr2[ch*16 + k]; }
        part[((size_t)blockIdx.x*64 + ch)*2]     = a;
        part[((size_t)blockIdx.x*64 + ch)*2 + 1] = b2;
    }
}

// ---------------- BN stat finalize (deterministic, double accumulation) -----
__global__ __launch_bounds__(256) void stats_kernel(const float* __restrict__ part,
                                                    int nblk, int cout,
                                                    const float* __restrict__ g,
                                                    const float* __restrict__ be,
                                                    float* __restrict__ A,
                                                    float* __restrict__ C)
{
    __shared__ double r1[256], r2[256];
    int ch = blockIdx.x, t = threadIdx.x;
    double s1 = 0.0, s2 = 0.0;
    for (int i = t; i < nblk; i += 256) {
        const float* p = part + ((size_t)i*cout + ch)*2;
        s1 += (double)p[0]; s2 += (double)p[1];
    }
    r1[t] = s1; r2[t] = s2; __syncthreads();
    for (int o = 128; o > 0; o >>= 1) {
        if (t < o) { r1[t] += r1[t+o]; r2[t] += r2[t+o]; }
        __syncthreads();
    }
    if (t == 0) {
        double n = (double)RTOT;
        double mean = r1[0] / n;
        double var  = r2[0] / n - mean*mean;
        float rstd = (float)(1.0 / sqrt(var + 1e-5));
        float a = g[ch] * rstd;
        float c = be[ch] - (float)mean * a;
        A[ch] = a; C[ch] = c;
    }
}

// ---------------- Mid conv: 64 -> 64, swizzled smem, float4 ------------------
template<int COUT>
__global__ __launch_bounds__(COUT*4, 1)
void conv_mid_kernel(const float* __restrict__ in,
                     const float* __restrict__ A, const float* __restrict__ C,
                     const float* __restrict__ W, const float* __restrict__ B,
                     float* __restrict__ out,
                     float* __restrict__ part)
{
    extern __shared__ float sm[];
    float* ins = sm;                 // [64][256] swizzled
    float* ws  = sm + 64*256;        // [COUT][65] padded
    float* sr1 = ws + COUT*65;       // [COUT][16]
    float* sr2 = sr1 + COUT*16;
    const int NT = COUT*4;
    int t = threadIdx.x; size_t r0 = (size_t)blockIdx.x * 256;

    for (int i = t; i < COUT*64; i += NT) { int o = i >> 6, c = i & 63; ws[o*65 + c] = W[i]; }
    for (int i = t; i < 64*64; i += NT) {
        int c = i >> 6, col4 = i & 63;
        float4 v = *reinterpret_cast<const float4*>(in + (size_t)c*RTOT + r0 + col4*4);
        float a = A[c], cc0 = C[c];
        v.x = fmaxf(fmaf(v.x, a, cc0), 0.f);
        v.y = fmaxf(fmaf(v.y, a, cc0), 0.f);
        v.z = fmaxf(fmaf(v.z, a, cc0), 0.f);
        v.w = fmaxf(fmaf(v.w, a, cc0), 0.f);
        *reinterpret_cast<float4*>(ins + c*256 + swz(col4)*4) = v;
    }
    __syncthreads();

    int colg = t & 15, chg = t >> 4;
    float acc[4][16];
#pragma unroll
    for (int cc = 0; cc < 4; cc++) {
        float bz = B[chg*4 + cc];
#pragma unroll
        for (int j = 0; j < 16; j++) acc[cc][j] = bz;
    }
    for (int c = 0; c < 64; c++) {
        float xv[16];
#pragma unroll
        for (int j = 0; j < 4; j++) {
            float4 v = *reinterpret_cast<const float4*>(ins + c*256 + swz(colg*4+j)*4);
            xv[4*j] = v.x; xv[4*j+1] = v.y; xv[4*j+2] = v.z; xv[4*j+3] = v.w;
        }
#pragma unroll
        for (int cc = 0; cc < 4; cc++) {
            float wv = ws[(chg*4 + cc)*65 + c];
#pragma unroll
            for (int j = 0; j < 16; j++) acc[cc][j] = fmaf(wv, xv[j], acc[cc][j]);
        }
    }
#pragma unroll
    for (int cc = 0; cc < 4; cc++) {
        int ch = chg*4 + cc;
        float s1 = 0.f, s2 = 0.f;
        float* o = out + (size_t)ch*RTOT + r0 + colg*16;
#pragma unroll
        for (int j = 0; j < 4; j++) {
            float4 v = make_float4(acc[cc][4*j], acc[cc][4*j+1], acc[cc][4*j+2], acc[cc][4*j+3]);
            *reinterpret_cast<float4*>(o + 4*j) = v;
        }
#pragma unroll
        for (int j = 0; j < 16; j++) { float v = acc[cc][j]; s1 += v; s2 = fmaf(v, v, s2); }
        sr1[ch*16 + colg] = s1; sr2[ch*16 + colg] = s2;
    }
    __syncthreads();
    for (int ch = t; ch < COUT; ch += NT) {
        float a = 0.f, b2 = 0.f;
#pragma unroll
        for (int k = 0; k < 16; k++) { a += sr1[ch*16 + k]; b2 += sr2[ch*16 + k]; }
        part[((size_t)blockIdx.x*COUT + ch)*2]     = a;
        part[((size_t)blockIdx.x*COUT + ch)*2 + 1] = b2;
    }
}

// ---------------- Last conv: 64 -> 128, swizzled, fused 32-group max ---------
__global__ __launch_bounds__(512, 1)
void conv_last_kernel(const float* __restrict__ in,
                      const float* __restrict__ A, const float* __restrict__ C,
                      const float* __restrict__ W, const float* __restrict__ B,
                      float* __restrict__ gmax,
                      float* __restrict__ part)
{
    extern __shared__ float sm[];
    float* ins = sm;                 // [64][256] swizzled
    float* ws  = sm + 64*256;        // [128][65]
    float* sr1 = ws + 128*65;        // [128][16]
    float* sr2 = sr1 + 128*16;
    const int NT = 512;
    int t = threadIdx.x; size_t r0 = (size_t)blockIdx.x * 256;

    for (int i = t; i < 128*64; i += NT) { int o = i >> 6, c = i & 63; ws[o*65 + c] = W[i]; }
    for (int i = t; i < 64*64; i += NT) {
        int c = i >> 6, col4 = i & 63;
        float4 v = *reinterpret_cast<const float4*>(in + (size_t)c*RTOT + r0 + col4*4);
        float a = A[c], cc0 = C[c];
        v.x = fmaxf(fmaf(v.x, a, cc0), 0.f);
        v.y = fmaxf(fmaf(v.y, a, cc0), 0.f);
        v.z = fmaxf(fmaf(v.z, a, cc0), 0.f);
        v.w = fmaxf(fmaf(v.w, a, cc0), 0.f);
        *reinterpret_cast<float4*>(ins + c*256 + swz(col4)*4) = v;
    }
    __syncthreads();

    int colg = t & 15, chg = t >> 4;
    float acc[4][16];
#pragma unroll
    for (int cc = 0; cc < 4; cc++) {
        float bz = B[chg*4 + cc];
#pragma unroll
        for (int j = 0; j < 16; j++) acc[cc][j] = bz;
    }
    for (int c = 0; c < 64; c++) {
        float xv[16];
#pragma unroll
        for (int j = 0; j < 4; j++) {
            float4 v = *reinterpret_cast<const float4*>(ins + c*256 + swz(colg*4+j)*4);
            xv[4*j] = v.x; xv[4*j+1] = v.y; xv[4*j+2] = v.z; xv[4*j+3] = v.w;
        }
#pragma unroll
        for (int cc = 0; cc < 4; cc++) {
            float wv = ws[(chg*4 + cc)*65 + c];
#pragma unroll
            for (int j = 0; j < 16; j++) acc[cc][j] = fmaf(wv, xv[j], acc[cc][j]);
        }
    }
#pragma unroll
    for (int cc = 0; cc < 4; cc++) {
        int ch = chg*4 + cc;
        float s1 = 0.f, s2 = 0.f;
        float m = acc[cc][0];
#pragma unroll
        for (int j = 0; j < 16; j++) {
            float v = acc[cc][j];
            s1 += v; s2 = fmaf(v, v, s2);
            m = fmaxf(m, v);
        }
        sr1[ch*16 + colg] = s1; sr2[ch*16 + colg] = s2;
        float om = __shfl_xor_sync(0xffffffffu, m, 1);   // partner half of 32-group
        m = fmaxf(m, om);
        if ((colg & 1) == 0) {
            size_t grp = (size_t)blockIdx.x*8 + (colg >> 1);
            gmax[grp*128 + ch] = m;
        }
    }
    __syncthreads();
    for (int ch = t; ch < 128; ch += NT) {
        float a = 0.f, b2 = 0.f;
#pragma unroll
        for (int k = 0; k < 16; k++) { a += sr1[ch*16 + k]; b2 += sr2[ch*16 + k]; }
        part[((size_t)blockIdx.x*128 + ch)*2]     = a;
        part[((size_t)blockIdx.x*128 + ch)*2 + 1] = b2;
    }
}

// ---------------- Finalize: out = relu(a * rawmax + c) ----------------------
__global__ __launch_bounds__(256) void finalize_kernel(const float* __restrict__ gmax,
                                                       const float* __restrict__ A,
                                                       const float* __restrict__ C,
                                                       float* __restrict__ dout)
{
    int i = blockIdx.x * 256 + threadIdx.x;
    int ch = i & 127;
    dout[(size_t)BATCH*NPOINT*3 + i] = fmaxf(fmaf(gmax[i], A[ch], C[ch]), 0.f);
}

// ---------------- launch ----------------------------------------------------
extern "C" void kernel_launch(void* const* d_in, const int* in_sizes, int n_in,
                              void* d_out, int out_size)
{
    (void)in_sizes; (void)n_in; (void)out_size;
    const float* xyz = (const float*)d_in[0];
    const float* pts = (const float*)d_in[1];
    const float* w0  = (const float*)d_in[2];  const float* b0  = (const float*)d_in[3];
    const float* g0  = (const float*)d_in[4];  const float* be0 = (const float*)d_in[5];
    const float* w1  = (const float*)d_in[6];  const float* b1  = (const float*)d_in[7];
    const float* g1  = (const float*)d_in[8];  const float* be1 = (const float*)d_in[9];
    const float* w2  = (const float*)d_in[10]; const float* b2  = (const float*)d_in[11];
    const float* g2  = (const float*)d_in[12]; const float* be2 = (const float*)d_in[13];
    float* out = (float*)d_out;

    float *y0, *y1, *gmax, *part, *A0, *C0, *A1, *C1, *A2, *C2;
    cudaGetSymbolAddress((void**)&y0,   g_y0);
    cudaGetSymbolAddress((void**)&y1,   g_y1);
    cudaGetSymbolAddress((void**)&gmax, g_gmax);
    cudaGetSymbolAddress((void**)&part, g_part);
    cudaGetSymbolAddress((void**)&A0,   g_A0);  cudaGetSymbolAddress((void**)&C0, g_C0);
    cudaGetSymbolAddress((void**)&A1,   g_A1);  cudaGetSymbolAddress((void**)&C1, g_C1);
    cudaGetSymbolAddress((void**)&A2,   g_A2);  cudaGetSymbolAddress((void**)&C2, g_C2);

    const int C1_SMEM  = (64*256 + 64*65  + 64*16*2)  * 4;       // 90368
    const int C2_SMEM  = (64*256 + 128*65 + 128*16*2) * 4;       // 115200
    cudaFuncSetAttribute(conv_mid_kernel<64>, cudaFuncAttributeMaxDynamicSharedMemorySize, C1_SMEM);
    cudaFuncSetAttribute(conv_last_kernel,    cudaFuncAttributeMaxDynamicSharedMemorySize, C2_SMEM);

    // launch order puts conv_mid<64> at ncu capture index 5 (2 harness fills
    // + fps + bqconv0 + stats precede it)
    fps_cluster_kernel<<<BATCH*FPB, FTH>>>(xyz, out);
    bqconv0_kernel<<<BATCH*NPOINT/8, 256>>>(xyz, pts, out, w0, b0, y0, part);
    stats_kernel<<<64, 256>>>(part, RTOT/256, 64, g0, be0, A0, C0);
    conv_mid_kernel<64><<<RTOT/256, 256, C1_SMEM>>>(y0, A0, C0, w1, b1, y1, part);
    stats_kernel<<<64, 256>>>(part, RTOT/256, 64, g1, be1, A1, C1);
    conv_last_kernel<<<RTOT/256, 512, C2_SMEM>>>(y1, A1, C1, w2, b2, gmax, part);
    stats_kernel<<<128, 256>>>(part, RTOT/256, 128, g2, be2, A2, C2);
    finalize_kernel<<<BATCH*NPOINT*128/256, 256>>>(gmax, A2, C2, out);
}